// round 7
// baseline (speedup 1.0000x reference)
#include <cuda_runtime.h>
#include <cstdint>
#include <math.h>

#define D_MODEL 512
#define N_HEADS 8
#define DK      64
#define BATCH   4
#define SEQ     2048
#define BT      (BATCH * SEQ)   // 8192
#define LN_EPS  1e-5f
#define PE_C    0.14391157f     // ln(10000)/64

// ---------------- scratch (device globals; no allocation allowed) -----------
__device__ float g_normed[BT * D_MODEL];   // tf32-rounded LN output
__device__ float g_q[BT * D_MODEL];        // [b][h][t][dk], tf32-rounded
__device__ float g_k[BT * D_MODEL];        // [b][h][t][dk], +PE, tf32-rounded
__device__ float g_vt[BT * D_MODEL];       // [b][h][dk][t], tf32-rounded
__device__ float g_ctx[BT * D_MODEL];      // [b][t][h*dk], tf32-rounded
__device__ float g_wr[4 * D_MODEL * D_MODEL];  // rounded wq,wk,wv,wo
__device__ float g_pe[SEQ * DK];           // sinusoidal PE table

// ---------------- PTX helpers ------------------------------------------------
__device__ __forceinline__ uint32_t smem_u32(const void* p) {
    return (uint32_t)__cvta_generic_to_shared((void*)p);
}
__device__ __forceinline__ uint32_t f2tf(float x) {
    uint32_t r; asm("cvt.rna.tf32.f32 %0, %1;" : "=r"(r) : "f"(x)); return r;
}
__device__ __forceinline__ float f2tff(float x) { return __uint_as_float(f2tf(x)); }

#define CP16(dst, src) \
    asm volatile("cp.async.cg.shared.global [%0], [%1], 16;" :: "r"(dst), "l"(src))
#define CP_COMMIT() asm volatile("cp.async.commit_group;" ::: "memory")
#define CP_WAIT1()  asm volatile("cp.async.wait_group 1;" ::: "memory")
#define CP_WAIT0()  asm volatile("cp.async.wait_group 0;" ::: "memory")

#define LDSM4(r0, r1, r2, r3, addr) \
    asm volatile("ldmatrix.sync.aligned.m8n8.x4.shared.b16 {%0,%1,%2,%3}, [%4];" \
        : "=r"(r0), "=r"(r1), "=r"(r2), "=r"(r3) : "r"(addr))

#define STS64(addr, a, b) \
    asm volatile("st.shared.v2.b32 [%0], {%1,%2};" :: "r"(addr), "r"(a), "r"(b))

// C (f32x4) += A(tf32 m16k8) * B(tf32 k8n8)
#define MMA_TF32(c, a, b) \
    asm volatile("mma.sync.aligned.m16n8k8.row.col.f32.tf32.tf32.f32 " \
        "{%0,%1,%2,%3}, {%4,%5,%6,%7}, {%8,%9}, {%0,%1,%2,%3};" \
        : "+f"((c)[0]), "+f"((c)[1]), "+f"((c)[2]), "+f"((c)[3]) \
        : "r"((a)[0]), "r"((a)[1]), "r"((a)[2]), "r"((a)[3]), \
          "r"((b)[0]), "r"((b)[1]))

// ---------------- weight rounding + PE table prep ----------------------------
__global__ void round_w(const float* __restrict__ wq, const float* __restrict__ wk,
                        const float* __restrict__ wv, const float* __restrict__ wo) {
    int i = blockIdx.x * 256 + threadIdx.x;       // 262144 per matrix
    g_wr[i]              = f2tff(wq[i]);
    g_wr[262144 + i]     = f2tff(wk[i]);
    g_wr[2 * 262144 + i] = f2tff(wv[i]);
    g_wr[3 * 262144 + i] = f2tff(wo[i]);
}

__global__ void pe_kernel() {
    int i = blockIdx.x * 256 + threadIdx.x;       // SEQ*DK = 131072
    int t = i >> 6, d = i & 63;
    float f = expf(-PE_C * (float)(d & ~1));
    float ang = (float)t * f;
    g_pe[i] = (d & 1) ? cosf(ang) : sinf(ang);
}

// ---------------- LayerNorm (rounds output to tf32) --------------------------
__global__ void ln_kernel(const float* __restrict__ x,
                          const float* __restrict__ gamma,
                          const float* __restrict__ beta) {
    int row = blockIdx.x;
    int tid = threadIdx.x;            // 256 threads
    const float* xr = x + (size_t)row * D_MODEL;
    float v0 = xr[tid];
    float v1 = xr[tid + 256];
    float s  = v0 + v1;
    float sq = v0 * v0 + v1 * v1;
    #pragma unroll
    for (int o = 16; o > 0; o >>= 1) {
        s  += __shfl_xor_sync(0xffffffffu, s,  o);
        sq += __shfl_xor_sync(0xffffffffu, sq, o);
    }
    __shared__ float ss[8], ssq[8];
    __shared__ float s_mu, s_rstd;
    int w = tid >> 5, l = tid & 31;
    if (l == 0) { ss[w] = s; ssq[w] = sq; }
    __syncthreads();
    if (tid == 0) {
        float S = 0.f, SQ = 0.f;
        #pragma unroll
        for (int i = 0; i < 8; i++) { S += ss[i]; SQ += ssq[i]; }
        float mu = S * (1.0f / D_MODEL);
        float var = SQ * (1.0f / D_MODEL) - mu * mu;
        s_mu = mu;
        s_rstd = rsqrtf(var + LN_EPS);
    }
    __syncthreads();
    float mu = s_mu, rs = s_rstd;
    float* out = g_normed + (size_t)row * D_MODEL;
    out[tid]       = f2tff((v0 - mu) * rs * gamma[tid]       + beta[tid]);
    out[tid + 256] = f2tff((v1 - mu) * rs * gamma[tid + 256] + beta[tid + 256]);
}

// ---------------- shared 128x128x512 tf32 mainloop ---------------------------
// 256 threads, 8 warps (2m x 4n), warp tile 64x32, BK=32, double-buffered.
// smem: A [2][128][32] swizzled @0 (32KB), B same @32768. Total 65536.
#define GEMM_SMEM 65536

__device__ __forceinline__ void gemm_mainloop(
    const float* __restrict__ A, const float* __restrict__ B,
    int m0, int n0, char* smem, float acc[4][4][4])
{
    uint32_t sA = smem_u32(smem), sB = sA + 32768;
    int tid = threadIdx.x, wid = tid >> 5, lane = tid & 31;
    int wm = (wid >> 2) * 64, wn = (wid & 3) * 32;

    #pragma unroll
    for (int i = 0; i < 4; i++) {
        int id = tid + i * 256, r = id >> 3, c = id & 7;
        uint32_t off = (uint32_t)((r * 8 + (c ^ (r & 7))) * 16);
        CP16(sA + off, A + (size_t)(m0 + r) * 512 + c * 4);
        CP16(sB + off, B + (size_t)(n0 + r) * 512 + c * 4);
    }
    CP_COMMIT();

    for (int itk = 0; itk < 16; itk++) {
        int buf = itk & 1;
        if (itk < 15) {
            int k0 = (itk + 1) * 32, nb = (itk + 1) & 1;
            #pragma unroll
            for (int i = 0; i < 4; i++) {
                int id = tid + i * 256, r = id >> 3, c = id & 7;
                uint32_t off = (uint32_t)(nb * 16384 + (r * 8 + (c ^ (r & 7))) * 16);
                CP16(sA + off, A + (size_t)(m0 + r) * 512 + k0 + c * 4);
                CP16(sB + off, B + (size_t)(n0 + r) * 512 + k0 + c * 4);
            }
            CP_COMMIT();
            CP_WAIT1();
        } else {
            CP_WAIT0();
        }
        __syncthreads();

        uint32_t ab = sA + buf * 16384, bb = sB + buf * 16384;
        #pragma unroll
        for (int ks = 0; ks < 4; ks++) {
            uint32_t af[4][4];
            #pragma unroll
            for (int mi = 0; mi < 4; mi++) {
                int r = wm + mi * 16 + (lane & 15);
                int c = 2 * ks + (lane >> 4);
                LDSM4(af[mi][0], af[mi][1], af[mi][2], af[mi][3],
                      ab + (r * 8 + (c ^ (r & 7))) * 16);
            }
            uint32_t bf[4][2];
            #pragma unroll
            for (int nj2 = 0; nj2 < 2; nj2++) {
                int r = wn + nj2 * 16 + (lane & 7) + ((lane >> 4) << 3);
                int c = 2 * ks + ((lane >> 3) & 1);
                uint32_t t0, t1, t2, t3;
                LDSM4(t0, t1, t2, t3, bb + (r * 8 + (c ^ (r & 7))) * 16);
                bf[nj2 * 2][0] = t0; bf[nj2 * 2][1] = t1;
                bf[nj2 * 2 + 1][0] = t2; bf[nj2 * 2 + 1][1] = t3;
            }
            #pragma unroll
            for (int mi = 0; mi < 4; mi++)
                #pragma unroll
                for (int nj = 0; nj < 4; nj++)
                    MMA_TF32(acc[mi][nj], af[mi], bf[nj]);
        }
        __syncthreads();
    }
}

// ---------------- QKV projection (+bias, +PE on K, head scatter) -------------
__global__ __launch_bounds__(256, 2) void qkv_tc(
    const float* __restrict__ bq, const float* __restrict__ bk,
    const float* __restrict__ bv)
{
    extern __shared__ char smem[];
    int tid = threadIdx.x, wid = tid >> 5, lane = tid & 31;
    int m0 = blockIdx.x * 128;
    int ng = blockIdx.y * 128;
    int wsel = ng >> 9, n0 = ng & 511;

    float acc[4][4][4];
    #pragma unroll
    for (int a = 0; a < 4; a++)
        #pragma unroll
        for (int b = 0; b < 4; b++)
            #pragma unroll
            for (int c = 0; c < 4; c++) acc[a][b][c] = 0.f;

    gemm_mainloop(g_normed, g_wr + (size_t)wsel * 262144, m0, n0, smem, acc);

    const float* bias = (wsel == 0) ? bq : (wsel == 1) ? bk : bv;
    int wm = (wid >> 2) * 64, wn = (wid & 3) * 32;
    #pragma unroll
    for (int mi = 0; mi < 4; mi++) {
        #pragma unroll
        for (int rr = 0; rr < 2; rr++) {
            int m = m0 + wm + mi * 16 + (lane >> 2) + rr * 8;
            int b = m >> 11, t = m & (SEQ - 1);
            #pragma unroll
            for (int nj = 0; nj < 4; nj++) {
                #pragma unroll
                for (int cc = 0; cc < 2; cc++) {
                    int n = n0 + wn + nj * 8 + (lane & 3) * 2 + cc;
                    float v = acc[mi][nj][rr * 2 + cc] + bias[n];
                    int h = n >> 6, d = n & 63;
                    size_t bh = (size_t)(b * N_HEADS + h);
                    if (wsel == 0) {
                        g_q[(bh * SEQ + t) * DK + d] = f2tff(v);
                    } else if (wsel == 1) {
                        v += g_pe[t * DK + d];
                        g_k[(bh * SEQ + t) * DK + d] = f2tff(v);
                    } else {
                        g_vt[(bh * DK + d) * SEQ + t] = f2tff(v);
                    }
                }
            }
        }
    }
}

// ---------------- output projection ------------------------------------------
__global__ __launch_bounds__(256, 2) void out_tc(const float* __restrict__ bo,
                                                 float* __restrict__ out)
{
    extern __shared__ char smem[];
    int tid = threadIdx.x, wid = tid >> 5, lane = tid & 31;
    int m0 = blockIdx.x * 128;
    int n0 = blockIdx.y * 128;

    float acc[4][4][4];
    #pragma unroll
    for (int a = 0; a < 4; a++)
        #pragma unroll
        for (int b = 0; b < 4; b++)
            #pragma unroll
            for (int c = 0; c < 4; c++) acc[a][b][c] = 0.f;

    gemm_mainloop(g_ctx, g_wr + 3 * 262144, m0, n0, smem, acc);

    int wm = (wid >> 2) * 64, wn = (wid & 3) * 32;
    #pragma unroll
    for (int mi = 0; mi < 4; mi++) {
        #pragma unroll
        for (int rr = 0; rr < 2; rr++) {
            int m = m0 + wm + mi * 16 + (lane >> 2) + rr * 8;
            #pragma unroll
            for (int nj = 0; nj < 4; nj++) {
                int n = n0 + wn + nj * 8 + (lane & 3) * 2;
                float2 v;
                v.x = acc[mi][nj][rr * 2]     + bo[n];
                v.y = acc[mi][nj][rr * 2 + 1] + bo[n + 1];
                *(float2*)(out + (size_t)m * 512 + n) = v;
            }
        }
    }
}

// ---------------- flash attention (tf32 mma.sync) ----------------------------
// CTA: 128 q-rows, 8 warps each owning m16. K/V tile = 64, double buffered.
// smem: Qs[128][64]@0 32KB, Ks[2][64][64]@32768 32KB, Vts[2][64][64]@65536 32KB,
//       Ps[128][32]@98304 16KB (PV runs in two k=32 halves, P buffer reused).
// Total 114688 B -> 2 CTAs/SM. All f32, XOR-swizzled 16B chunks.
#define ATTN_SMEM 114688

__global__ __launch_bounds__(256, 2) void attn_tc() {
    extern __shared__ char smem[];
    uint32_t sQ = smem_u32(smem);
    uint32_t sK = sQ + 32768;
    uint32_t sV = sQ + 65536;
    uint32_t sP = sQ + 98304;
    int tid = threadIdx.x, wid = tid >> 5, lane = tid & 31;
    int bh = blockIdx.z * N_HEADS + blockIdx.y;
    int q0 = blockIdx.x * 128;
    const float* Qb  = g_q  + (size_t)bh * SEQ * DK;
    const float* Kb  = g_k  + (size_t)bh * SEQ * DK;
    const float* Vtb = g_vt + (size_t)bh * DK * SEQ;

    // stage Q [128 x 64] : 2048 chunks of 16B
    #pragma unroll
    for (int i = 0; i < 8; i++) {
        int id = tid + i * 256, r = id >> 4, c = id & 15;
        CP16(sQ + (r * 16 + (c ^ (r & 7))) * 16, Qb + (size_t)(q0 + r) * DK + c * 4);
    }
    CP_COMMIT();
    // stage K/V tile 0
    #pragma unroll
    for (int i = 0; i < 4; i++) {
        int id = tid + i * 256, r = id >> 4, c = id & 15;
        uint32_t off = (r * 16 + (c ^ (r & 7))) * 16;
        CP16(sK + off, Kb + (size_t)r * DK + c * 4);
        CP16(sV + off, Vtb + (size_t)r * SEQ + c * 4);
    }
    CP_COMMIT();

    float accO[8][4];
    #pragma unroll
    for (int nj = 0; nj < 8; nj++)
        #pragma unroll
        for (int k = 0; k < 4; k++) accO[nj][k] = 0.f;
    float mrun0 = -1e30f, mrun1 = -1e30f, l0 = 0.f, l1 = 0.f;

    for (int it = 0; it < 32; it++) {
        int buf = it & 1;
        if (it < 31) {
            int s0 = (it + 1) * 64, nb = (it + 1) & 1;
            #pragma unroll
            for (int i = 0; i < 4; i++) {
                int id = tid + i * 256, r = id >> 4, c = id & 15;
                uint32_t off = nb * 16384 + (r * 16 + (c ^ (r & 7))) * 16;
                CP16(sK + off, Kb + (size_t)(s0 + r) * DK + c * 4);
                CP16(sV + off, Vtb + (size_t)r * SEQ + s0 + c * 4);
            }
            CP_COMMIT();
            CP_WAIT1();
        } else {
            CP_WAIT0();
        }
        __syncthreads();

        uint32_t kb = sK + buf * 16384, vb = sV + buf * 16384;

        // ---- S = Q @ K^T : per-warp m16 x n64, k=64 (8 ksteps) ----
        float s[8][4];
        #pragma unroll
        for (int nj = 0; nj < 8; nj++)
            #pragma unroll
            for (int k = 0; k < 4; k++) s[nj][k] = 0.f;
        #pragma unroll
        for (int ks = 0; ks < 8; ks++) {
            uint32_t af[4];
            {
                int r = wid * 16 + (lane & 15);
                int c = 2 * ks + (lane >> 4);
                LDSM4(af[0], af[1], af[2], af[3], sQ + (r * 16 + (c ^ (r & 7))) * 16);
            }
            #pragma unroll
            for (int nj2 = 0; nj2 < 4; nj2++) {
                int r = nj2 * 16 + (lane & 7) + ((lane >> 4) << 3);
                int c = 2 * ks + ((lane >> 3) & 1);
                uint32_t t0, t1, t2, t3;
                LDSM4(t0, t1, t2, t3, kb + (r * 16 + (c ^ (r & 7))) * 16);
                uint32_t b0[2] = {t0, t1}, b1[2] = {t2, t3};
                MMA_TF32(s[nj2 * 2], af, b0);
                MMA_TF32(s[nj2 * 2 + 1], af, b1);
            }
        }

        // ---- online softmax (rows g and g+8 per lane) ----
        #pragma unroll
        for (int nj = 0; nj < 8; nj++)
            #pragma unroll
            for (int k = 0; k < 4; k++) s[nj][k] *= 0.125f;
        float ml0 = -1e30f, ml1 = -1e30f;
        #pragma unroll
        for (int nj = 0; nj < 8; nj++) {
            ml0 = fmaxf(ml0, fmaxf(s[nj][0], s[nj][1]));
            ml1 = fmaxf(ml1, fmaxf(s[nj][2], s[nj][3]));
        }
        ml0 = fmaxf(ml0, __shfl_xor_sync(0xffffffffu, ml0, 1));
        ml0 = fmaxf(ml0, __shfl_xor_sync(0xffffffffu, ml0, 2));
        ml1 = fmaxf(ml1, __shfl_xor_sync(0xffffffffu, ml1, 1));
        ml1 = fmaxf(ml1, __shfl_xor_sync(0xffffffffu, ml1, 2));
        float mn0 = fmaxf(mrun0, ml0), mn1 = fmaxf(mrun1, ml1);
        float al0 = __expf(mrun0 - mn0), al1 = __expf(mrun1 - mn1);
        float rs0 = 0.f, rs1 = 0.f;
        #pragma unroll
        for (int nj = 0; nj < 8; nj++) {
            s[nj][0] = __expf(s[nj][0] - mn0);
            s[nj][1] = __expf(s[nj][1] - mn0);
            s[nj][2] = __expf(s[nj][2] - mn1);
            s[nj][3] = __expf(s[nj][3] - mn1);
            rs0 += s[nj][0] + s[nj][1];
            rs1 += s[nj][2] + s[nj][3];
        }
        rs0 += __shfl_xor_sync(0xffffffffu, rs0, 1);
        rs0 += __shfl_xor_sync(0xffffffffu, rs0, 2);
        rs1 += __shfl_xor_sync(0xffffffffu, rs1, 1);
        rs1 += __shfl_xor_sync(0xffffffffu, rs1, 2);
        l0 = l0 * al0 + rs0;  l1 = l1 * al1 + rs1;
        mrun0 = mn0;          mrun1 = mn1;
        #pragma unroll
        for (int nj = 0; nj < 8; nj++) {
            accO[nj][0] *= al0; accO[nj][1] *= al0;
            accO[nj][2] *= al1; accO[nj][3] *= al1;
        }

        // ---- O += P @ V in two k=32 halves; P staged via 16KB buffer ----
        #pragma unroll
        for (int h = 0; h < 2; h++) {
            __syncwarp();
            {
                int r0 = wid * 16 + (lane >> 2), r1 = r0 + 8;
                int off8 = (lane & 1) * 8;
                #pragma unroll
                for (int njl = 0; njl < 4; njl++) {
                    int nj = h * 4 + njl;
                    int col = njl * 8 + (lane & 3) * 2;
                    int ch = col >> 2;
                    STS64(sP + (r0 * 8 + (ch ^ (r0 & 7))) * 16 + off8,
                          f2tf(s[nj][0]), f2tf(s[nj][1]));
                    STS64(sP + (r1 * 8 + (ch ^ (r1 & 7))) * 16 + off8,
                          f2tf(s[nj][2]), f2tf(s[nj][3]));
                }
            }
            __syncwarp();
            #pragma unroll
            for (int ksl = 0; ksl < 4; ksl++) {
                int ks = h * 4 + ksl;
                uint32_t af[4];
                {
                    int r = wid * 16 + (lane & 15);
                    int c = 2 * ksl + (lane >> 4);
                    LDSM4(af[0], af[1], af[2], af[3], sP + (r * 8 + (c ^ (r & 7))) * 16);
                }
                #pragma unroll
                for (int nj2 = 0; nj2 < 4; nj2++) {
                    int r = nj2 * 16 + (lane & 7) + ((lane >> 4) << 3);
                    int c = 2 * ks + ((lane >> 3) & 1);
                    uint32_t t0, t1, t2, t3;
                    LDSM4(t0, t1, t2, t3, vb + (r * 16 + (c ^ (r & 7))) * 16);
                    uint32_t b0[2] = {t0, t1}, b1[2] = {t2, t3};
                    MMA_TF32(accO[nj2 * 2], af, b0);
                    MMA_TF32(accO[nj2 * 2 + 1], af, b1);
                }
            }
        }
        __syncthreads();
    }

    // ---- epilogue: normalize, round, write to g_ctx ----
    float inv0 = 1.0f / l0, inv1 = 1.0f / l1;
    int t0 = q0 + wid * 16 + (lane >> 2), t1 = t0 + 8;
    float* dst = g_ctx + (size_t)blockIdx.z * SEQ * D_MODEL + (size_t)blockIdx.y * DK;
    #pragma unroll
    for (int nj = 0; nj < 8; nj++) {
        int col = nj * 8 + (lane & 3) * 2;
        float2 v0, v1;
        v0.x = f2tff(accO[nj][0] * inv0); v0.y = f2tff(accO[nj][1] * inv0);
        v1.x = f2tff(accO[nj][2] * inv1); v1.y = f2tff(accO[nj][3] * inv1);
        *(float2*)(dst + (size_t)t0 * D_MODEL + col) = v0;
        *(float2*)(dst + (size_t)t1 * D_MODEL + col) = v1;
    }
}

// ---------------- launch -----------------------------------------------------
extern "C" void kernel_launch(void* const* d_in, const int* in_sizes, int n_in,
                              void* d_out, int out_size) {
    const float* x    = (const float*)d_in[0];
    const float* ln_g = (const float*)d_in[1];
    const float* ln_b = (const float*)d_in[2];
    const float* wq   = (const float*)d_in[3];
    const float* bq   = (const float*)d_in[4];
    const float* wk   = (const float*)d_in[5];
    const float* bk   = (const float*)d_in[6];
    const float* wv   = (const float*)d_in[7];
    const float* bv   = (const float*)d_in[8];
    const float* wo   = (const float*)d_in[9];
    const float* bo   = (const float*)d_in[10];

    cudaFuncSetAttribute(qkv_tc,  cudaFuncAttributeMaxDynamicSharedMemorySize, GEMM_SMEM);
    cudaFuncSetAttribute(out_tc,  cudaFuncAttributeMaxDynamicSharedMemorySize, GEMM_SMEM);
    cudaFuncSetAttribute(attn_tc, cudaFuncAttributeMaxDynamicSharedMemorySize, ATTN_SMEM);

    round_w<<<1024, 256>>>(wq, wk, wv, wo);
    pe_kernel<<<512, 256>>>();
    ln_kernel<<<BT, 256>>>(x, ln_g, ln_b);
    qkv_tc<<<dim3(64, 12), 256, GEMM_SMEM>>>(bq, bk, bv);
    attn_tc<<<dim3(16, 8, 4), 256, ATTN_SMEM>>>();
    out_tc<<<dim3(64, 4), 256, GEMM_SMEM>>>(bo, (float*)d_out);
}

// round 10
// speedup vs baseline: 1.3830x; 1.3830x over previous
#include <cuda_runtime.h>
#include <cstdint>
#include <math.h>

#define D_MODEL 512
#define N_HEADS 8
#define DK      64
#define BATCH   4
#define SEQ     2048
#define BT      (BATCH * SEQ)   // 8192
#define LN_EPS  1e-5f
#define PE_C    0.14391157f     // ln(10000)/64

// ---------------- scratch (device globals; no allocation allowed) -----------
__device__ float g_normed[BT * D_MODEL];   // tf32-rounded LN output
__device__ float g_q[BT * D_MODEL];        // [b][h][t][dk], tf32-rounded
__device__ float g_k[BT * D_MODEL];        // [b][h][t][dk], +PE, tf32-rounded
__device__ float g_vt[BT * D_MODEL];       // [b][h][dk][t], tf32-rounded
__device__ float g_ctx[BT * D_MODEL];      // [b][t][h*dk], tf32-rounded
__device__ float g_wr[4 * D_MODEL * D_MODEL];  // rounded wq,wk,wv,wo
__device__ float g_pe[SEQ * DK];           // sinusoidal PE table

// ---------------- PTX helpers ------------------------------------------------
__device__ __forceinline__ uint32_t smem_u32(const void* p) {
    return (uint32_t)__cvta_generic_to_shared((void*)p);
}
__device__ __forceinline__ uint32_t f2tf(float x) {
    uint32_t r; asm("cvt.rna.tf32.f32 %0, %1;" : "=r"(r) : "f"(x)); return r;
}
__device__ __forceinline__ float f2tff(float x) { return __uint_as_float(f2tf(x)); }

#define CP16(dst, src) \
    asm volatile("cp.async.cg.shared.global [%0], [%1], 16;" :: "r"(dst), "l"(src))
#define CP_COMMIT() asm volatile("cp.async.commit_group;" ::: "memory")
#define CP_WAIT1()  asm volatile("cp.async.wait_group 1;" ::: "memory")
#define CP_WAIT0()  asm volatile("cp.async.wait_group 0;" ::: "memory")

#define LDSM4(r0, r1, r2, r3, addr) \
    asm volatile("ldmatrix.sync.aligned.m8n8.x4.shared.b16 {%0,%1,%2,%3}, [%4];" \
        : "=r"(r0), "=r"(r1), "=r"(r2), "=r"(r3) : "r"(addr))

#define STS64(addr, a, b) \
    asm volatile("st.shared.v2.b32 [%0], {%1,%2};" :: "r"(addr), "r"(a), "r"(b))

// C (f32x4) += A(tf32 m16k8) * B(tf32 k8n8)
#define MMA_TF32(c, a, b) \
    asm volatile("mma.sync.aligned.m16n8k8.row.col.f32.tf32.tf32.f32 " \
        "{%0,%1,%2,%3}, {%4,%5,%6,%7}, {%8,%9}, {%0,%1,%2,%3};" \
        : "+f"((c)[0]), "+f"((c)[1]), "+f"((c)[2]), "+f"((c)[3]) \
        : "r"((a)[0]), "r"((a)[1]), "r"((a)[2]), "r"((a)[3]), \
          "r"((b)[0]), "r"((b)[1]))

// ---------------- weight rounding + PE table prep ----------------------------
__global__ void round_w(const float* __restrict__ wq, const float* __restrict__ wk,
                        const float* __restrict__ wv, const float* __restrict__ wo) {
    int i = blockIdx.x * 256 + threadIdx.x;       // 262144 per matrix
    g_wr[i]              = f2tff(wq[i]);
    g_wr[262144 + i]     = f2tff(wk[i]);
    g_wr[2 * 262144 + i] = f2tff(wv[i]);
    g_wr[3 * 262144 + i] = f2tff(wo[i]);
}

__global__ void pe_kernel() {
    int i = blockIdx.x * 256 + threadIdx.x;       // SEQ*DK = 131072
    int t = i >> 6, d = i & 63;
    float f = expf(-PE_C * (float)(d & ~1));
    float ang = (float)t * f;
    g_pe[i] = (d & 1) ? cosf(ang) : sinf(ang);
}

// ---------------- LayerNorm (rounds output to tf32) --------------------------
__global__ void ln_kernel(const float* __restrict__ x,
                          const float* __restrict__ gamma,
                          const float* __restrict__ beta) {
    int row = blockIdx.x;
    int tid = threadIdx.x;            // 256 threads
    const float* xr = x + (size_t)row * D_MODEL;
    float v0 = xr[tid];
    float v1 = xr[tid + 256];
    float s  = v0 + v1;
    float sq = v0 * v0 + v1 * v1;
    #pragma unroll
    for (int o = 16; o > 0; o >>= 1) {
        s  += __shfl_xor_sync(0xffffffffu, s,  o);
        sq += __shfl_xor_sync(0xffffffffu, sq, o);
    }
    __shared__ float ss[8], ssq[8];
    __shared__ float s_mu, s_rstd;
    int w = tid >> 5, l = tid & 31;
    if (l == 0) { ss[w] = s; ssq[w] = sq; }
    __syncthreads();
    if (tid == 0) {
        float S = 0.f, SQ = 0.f;
        #pragma unroll
        for (int i = 0; i < 8; i++) { S += ss[i]; SQ += ssq[i]; }
        float mu = S * (1.0f / D_MODEL);
        float var = SQ * (1.0f / D_MODEL) - mu * mu;
        s_mu = mu;
        s_rstd = rsqrtf(var + LN_EPS);
    }
    __syncthreads();
    float mu = s_mu, rs = s_rstd;
    float* out = g_normed + (size_t)row * D_MODEL;
    out[tid]       = f2tff((v0 - mu) * rs * gamma[tid]       + beta[tid]);
    out[tid + 256] = f2tff((v1 - mu) * rs * gamma[tid + 256] + beta[tid + 256]);
}

// ---------------- shared 128x128x512 tf32 mainloop ---------------------------
// 256 threads, 8 warps (2m x 4n), warp tile 64x32, BK=32, double-buffered.
// smem: A [2][128][32] swizzled @0 (32KB), B same @32768. Total 65536.
#define GEMM_SMEM 65536

__device__ __forceinline__ void gemm_mainloop(
    const float* __restrict__ A, const float* __restrict__ B,
    int m0, int n0, char* smem, float acc[4][4][4])
{
    uint32_t sA = smem_u32(smem), sB = sA + 32768;
    int tid = threadIdx.x, wid = tid >> 5, lane = tid & 31;
    int wm = (wid >> 2) * 64, wn = (wid & 3) * 32;

    #pragma unroll
    for (int i = 0; i < 4; i++) {
        int id = tid + i * 256, r = id >> 3, c = id & 7;
        uint32_t off = (uint32_t)((r * 8 + (c ^ (r & 7))) * 16);
        CP16(sA + off, A + (size_t)(m0 + r) * 512 + c * 4);
        CP16(sB + off, B + (size_t)(n0 + r) * 512 + c * 4);
    }
    CP_COMMIT();

    for (int itk = 0; itk < 16; itk++) {
        int buf = itk & 1;
        if (itk < 15) {
            int k0 = (itk + 1) * 32, nb = (itk + 1) & 1;
            #pragma unroll
            for (int i = 0; i < 4; i++) {
                int id = tid + i * 256, r = id >> 3, c = id & 7;
                uint32_t off = (uint32_t)(nb * 16384 + (r * 8 + (c ^ (r & 7))) * 16);
                CP16(sA + off, A + (size_t)(m0 + r) * 512 + k0 + c * 4);
                CP16(sB + off, B + (size_t)(n0 + r) * 512 + k0 + c * 4);
            }
            CP_COMMIT();
            CP_WAIT1();
        } else {
            CP_WAIT0();
        }
        __syncthreads();

        uint32_t ab = sA + buf * 16384, bb = sB + buf * 16384;
        #pragma unroll
        for (int ks = 0; ks < 4; ks++) {
            uint32_t af[4][4];
            #pragma unroll
            for (int mi = 0; mi < 4; mi++) {
                int r = wm + mi * 16 + (lane & 15);
                int c = 2 * ks + (lane >> 4);
                LDSM4(af[mi][0], af[mi][1], af[mi][2], af[mi][3],
                      ab + (r * 8 + (c ^ (r & 7))) * 16);
            }
            uint32_t bf[4][2];
            #pragma unroll
            for (int nj2 = 0; nj2 < 2; nj2++) {
                int r = wn + nj2 * 16 + (lane & 7) + ((lane >> 4) << 3);
                int c = 2 * ks + ((lane >> 3) & 1);
                uint32_t t0, t1, t2, t3;
                LDSM4(t0, t1, t2, t3, bb + (r * 8 + (c ^ (r & 7))) * 16);
                bf[nj2 * 2][0] = t0; bf[nj2 * 2][1] = t1;
                bf[nj2 * 2 + 1][0] = t2; bf[nj2 * 2 + 1][1] = t3;
            }
            #pragma unroll
            for (int mi = 0; mi < 4; mi++)
                #pragma unroll
                for (int nj = 0; nj < 4; nj++)
                    MMA_TF32(acc[mi][nj], af[mi], bf[nj]);
        }
        __syncthreads();
    }
}

// ---------------- QKV projection (+bias, +PE on K, head scatter) -------------
__global__ __launch_bounds__(256) void qkv_tc(
    const float* __restrict__ bq, const float* __restrict__ bk,
    const float* __restrict__ bv)
{
    extern __shared__ char smem[];
    int tid = threadIdx.x, wid = tid >> 5, lane = tid & 31;
    int m0 = blockIdx.x * 128;
    int ng = blockIdx.y * 128;
    int wsel = ng >> 9, n0 = ng & 511;

    float acc[4][4][4];
    #pragma unroll
    for (int a = 0; a < 4; a++)
        #pragma unroll
        for (int b = 0; b < 4; b++)
            #pragma unroll
            for (int c = 0; c < 4; c++) acc[a][b][c] = 0.f;

    gemm_mainloop(g_normed, g_wr + (size_t)wsel * 262144, m0, n0, smem, acc);

    const float* bias = (wsel == 0) ? bq : (wsel == 1) ? bk : bv;
    int wm = (wid >> 2) * 64, wn = (wid & 3) * 32;
    #pragma unroll
    for (int mi = 0; mi < 4; mi++) {
        #pragma unroll
        for (int rr = 0; rr < 2; rr++) {
            int m = m0 + wm + mi * 16 + (lane >> 2) + rr * 8;
            int b = m >> 11, t = m & (SEQ - 1);
            #pragma unroll
            for (int nj = 0; nj < 4; nj++) {
                #pragma unroll
                for (int cc = 0; cc < 2; cc++) {
                    int n = n0 + wn + nj * 8 + (lane & 3) * 2 + cc;
                    float v = acc[mi][nj][rr * 2 + cc] + bias[n];
                    int h = n >> 6, d = n & 63;
                    size_t bh = (size_t)(b * N_HEADS + h);
                    if (wsel == 0) {
                        g_q[(bh * SEQ + t) * DK + d] = f2tff(v);
                    } else if (wsel == 1) {
                        v += g_pe[t * DK + d];
                        g_k[(bh * SEQ + t) * DK + d] = f2tff(v);
                    } else {
                        g_vt[(bh * DK + d) * SEQ + t] = f2tff(v);
                    }
                }
            }
        }
    }
}

// ---------------- output projection ------------------------------------------
__global__ __launch_bounds__(256) void out_tc(const float* __restrict__ bo,
                                              float* __restrict__ out)
{
    extern __shared__ char smem[];
    int tid = threadIdx.x, wid = tid >> 5, lane = tid & 31;
    int m0 = blockIdx.x * 128;
    int n0 = blockIdx.y * 128;

    float acc[4][4][4];
    #pragma unroll
    for (int a = 0; a < 4; a++)
        #pragma unroll
        for (int b = 0; b < 4; b++)
            #pragma unroll
            for (int c = 0; c < 4; c++) acc[a][b][c] = 0.f;

    gemm_mainloop(g_ctx, g_wr + 3 * 262144, m0, n0, smem, acc);

    int wm = (wid >> 2) * 64, wn = (wid & 3) * 32;
    #pragma unroll
    for (int mi = 0; mi < 4; mi++) {
        #pragma unroll
        for (int rr = 0; rr < 2; rr++) {
            int m = m0 + wm + mi * 16 + (lane >> 2) + rr * 8;
            #pragma unroll
            for (int nj = 0; nj < 4; nj++) {
                int n = n0 + wn + nj * 8 + (lane & 3) * 2;
                float2 v;
                v.x = acc[mi][nj][rr * 2]     + bo[n];
                v.y = acc[mi][nj][rr * 2 + 1] + bo[n + 1];
                *(float2*)(out + (size_t)m * 512 + n) = v;
            }
        }
    }
}

// ---------------- flash attention (tf32 mma.sync) ----------------------------
// CTA: 64 q-rows, 128 threads (4 warps each owning m16). K/V tile = 64, db.
// smem: Qs[64][64]@0 16KB, Ks[2][64][64]@16384 32KB, Vts[2][64][64]@49152 32KB,
//       Ps[64][64]@81920 16KB. Total 98304 B -> 2 CTAs/SM by smem, regs free.
#define ATTN_SMEM 98304

__global__ __launch_bounds__(128) void attn_tc() {
    extern __shared__ char smem[];
    uint32_t sQ = smem_u32(smem);
    uint32_t sK = sQ + 16384;
    uint32_t sV = sQ + 49152;
    uint32_t sP = sQ + 81920;
    int tid = threadIdx.x, wid = tid >> 5, lane = tid & 31;
    int bh = blockIdx.z * N_HEADS + blockIdx.y;
    int q0 = blockIdx.x * 64;
    const float* Qb  = g_q  + (size_t)bh * SEQ * DK;
    const float* Kb  = g_k  + (size_t)bh * SEQ * DK;
    const float* Vtb = g_vt + (size_t)bh * DK * SEQ;

    // stage Q [64 x 64] : 1024 chunks of 16B over 128 threads
    #pragma unroll
    for (int i = 0; i < 8; i++) {
        int id = tid + i * 128, r = id >> 4, c = id & 15;
        CP16(sQ + (r * 16 + (c ^ (r & 7))) * 16, Qb + (size_t)(q0 + r) * DK + c * 4);
    }
    CP_COMMIT();
    // stage K/V tile 0
    #pragma unroll
    for (int i = 0; i < 8; i++) {
        int id = tid + i * 128, r = id >> 4, c = id & 15;
        uint32_t off = (r * 16 + (c ^ (r & 7))) * 16;
        CP16(sK + off, Kb + (size_t)r * DK + c * 4);
        CP16(sV + off, Vtb + (size_t)r * SEQ + c * 4);
    }
    CP_COMMIT();

    float accO[8][4];
    #pragma unroll
    for (int nj = 0; nj < 8; nj++)
        #pragma unroll
        for (int k = 0; k < 4; k++) accO[nj][k] = 0.f;
    float mrun0 = -1e30f, mrun1 = -1e30f, l0 = 0.f, l1 = 0.f;

    for (int it = 0; it < 32; it++) {
        int buf = it & 1;
        if (it < 31) {
            int s0 = (it + 1) * 64, nb = (it + 1) & 1;
            #pragma unroll
            for (int i = 0; i < 8; i++) {
                int id = tid + i * 128, r = id >> 4, c = id & 15;
                uint32_t off = nb * 16384 + (r * 16 + (c ^ (r & 7))) * 16;
                CP16(sK + off, Kb + (size_t)(s0 + r) * DK + c * 4);
                CP16(sV + off, Vtb + (size_t)r * SEQ + s0 + c * 4);
            }
            CP_COMMIT();
            CP_WAIT1();
        } else {
            CP_WAIT0();
        }
        __syncthreads();

        uint32_t kb = sK + buf * 16384, vb = sV + buf * 16384;

        // ---- S = Q @ K^T : per-warp m16 x n64, k=64 (8 ksteps) ----
        float s[8][4];
        #pragma unroll
        for (int nj = 0; nj < 8; nj++)
            #pragma unroll
            for (int k = 0; k < 4; k++) s[nj][k] = 0.f;
        #pragma unroll
        for (int ks = 0; ks < 8; ks++) {
            uint32_t af[4];
            {
                int r = wid * 16 + (lane & 15);
                int c = 2 * ks + (lane >> 4);
                LDSM4(af[0], af[1], af[2], af[3], sQ + (r * 16 + (c ^ (r & 7))) * 16);
            }
            #pragma unroll
            for (int nj2 = 0; nj2 < 4; nj2++) {
                int r = nj2 * 16 + (lane & 7) + ((lane >> 4) << 3);
                int c = 2 * ks + ((lane >> 3) & 1);
                uint32_t t0, t1, t2, t3;
                LDSM4(t0, t1, t2, t3, kb + (r * 16 + (c ^ (r & 7))) * 16);
                uint32_t b0[2] = {t0, t1}, b1[2] = {t2, t3};
                MMA_TF32(s[nj2 * 2], af, b0);
                MMA_TF32(s[nj2 * 2 + 1], af, b1);
            }
        }

        // ---- online softmax (rows g and g+8 per lane) ----
        #pragma unroll
        for (int nj = 0; nj < 8; nj++)
            #pragma unroll
            for (int k = 0; k < 4; k++) s[nj][k] *= 0.125f;
        float ml0 = -1e30f, ml1 = -1e30f;
        #pragma unroll
        for (int nj = 0; nj < 8; nj++) {
            ml0 = fmaxf(ml0, fmaxf(s[nj][0], s[nj][1]));
            ml1 = fmaxf(ml1, fmaxf(s[nj][2], s[nj][3]));
        }
        ml0 = fmaxf(ml0, __shfl_xor_sync(0xffffffffu, ml0, 1));
        ml0 = fmaxf(ml0, __shfl_xor_sync(0xffffffffu, ml0, 2));
        ml1 = fmaxf(ml1, __shfl_xor_sync(0xffffffffu, ml1, 1));
        ml1 = fmaxf(ml1, __shfl_xor_sync(0xffffffffu, ml1, 2));
        float mn0 = fmaxf(mrun0, ml0), mn1 = fmaxf(mrun1, ml1);
        float al0 = __expf(mrun0 - mn0), al1 = __expf(mrun1 - mn1);
        float rs0 = 0.f, rs1 = 0.f;
        #pragma unroll
        for (int nj = 0; nj < 8; nj++) {
            s[nj][0] = __expf(s[nj][0] - mn0);
            s[nj][1] = __expf(s[nj][1] - mn0);
            s[nj][2] = __expf(s[nj][2] - mn1);
            s[nj][3] = __expf(s[nj][3] - mn1);
            rs0 += s[nj][0] + s[nj][1];
            rs1 += s[nj][2] + s[nj][3];
        }
        rs0 += __shfl_xor_sync(0xffffffffu, rs0, 1);
        rs0 += __shfl_xor_sync(0xffffffffu, rs0, 2);
        rs1 += __shfl_xor_sync(0xffffffffu, rs1, 1);
        rs1 += __shfl_xor_sync(0xffffffffu, rs1, 2);
        l0 = l0 * al0 + rs0;  l1 = l1 * al1 + rs1;
        mrun0 = mn0;          mrun1 = mn1;
        #pragma unroll
        for (int nj = 0; nj < 8; nj++) {
            accO[nj][0] *= al0; accO[nj][1] *= al0;
            accO[nj][2] *= al1; accO[nj][3] *= al1;
        }

        // ---- store P (tf32-rounded) to smem in A-operand layout ----
        {
            int r0 = wid * 16 + (lane >> 2), r1 = r0 + 8;
            int off8 = (lane & 1) * 8;
            #pragma unroll
            for (int nj = 0; nj < 8; nj++) {
                int col = nj * 8 + (lane & 3) * 2;
                int ch = col >> 2;
                STS64(sP + (r0 * 16 + (ch ^ (r0 & 7))) * 16 + off8,
                      f2tf(s[nj][0]), f2tf(s[nj][1]));
                STS64(sP + (r1 * 16 + (ch ^ (r1 & 7))) * 16 + off8,
                      f2tf(s[nj][2]), f2tf(s[nj][3]));
            }
        }
        __syncwarp();

        // ---- O += P @ V : per-warp m16 x n64(d), k=64(s) ----
        #pragma unroll
        for (int ks = 0; ks < 8; ks++) {
            uint32_t af[4];
            {
                int r = wid * 16 + (lane & 15);
                int c = 2 * ks + (lane >> 4);
                LDSM4(af[0], af[1], af[2], af[3], sP + (r * 16 + (c ^ (r & 7))) * 16);
            }
            #pragma unroll
            for (int nj2 = 0; nj2 < 4; nj2++) {
                int r = nj2 * 16 + (lane & 7) + ((lane >> 4) << 3);
                int c = 2 * ks + ((lane >> 3) & 1);
                uint32_t t0, t1, t2, t3;
                LDSM4(t0, t1, t2, t3, vb + (r * 16 + (c ^ (r & 7))) * 16);
                uint32_t b0[2] = {t0, t1}, b1[2] = {t2, t3};
                MMA_TF32(accO[nj2 * 2], af, b0);
                MMA_TF32(accO[nj2 * 2 + 1], af, b1);
            }
        }
        __syncthreads();
    }

    // ---- epilogue: normalize, round, write to g_ctx ----
    float inv0 = 1.0f / l0, inv1 = 1.0f / l1;
    int t0 = q0 + wid * 16 + (lane >> 2), t1 = t0 + 8;
    float* dst = g_ctx + (size_t)blockIdx.z * SEQ * D_MODEL + (size_t)blockIdx.y * DK;
    #pragma unroll
    for (int nj = 0; nj < 8; nj++) {
        int col = nj * 8 + (lane & 3) * 2;
        float2 v0, v1;
        v0.x = f2tff(accO[nj][0] * inv0); v0.y = f2tff(accO[nj][1] * inv0);
        v1.x = f2tff(accO[nj][2] * inv1); v1.y = f2tff(accO[nj][3] * inv1);
        *(float2*)(dst + (size_t)t0 * D_MODEL + col) = v0;
        *(float2*)(dst + (size_t)t1 * D_MODEL + col) = v1;
    }
}

// ---------------- launch -----------------------------------------------------
extern "C" void kernel_launch(void* const* d_in, const int* in_sizes, int n_in,
                              void* d_out, int out_size) {
    const float* x    = (const float*)d_in[0];
    const float* ln_g = (const float*)d_in[1];
    const float* ln_b = (const float*)d_in[2];
    const float* wq   = (const float*)d_in[3];
    const float* bq   = (const float*)d_in[4];
    const float* wk   = (const float*)d_in[5];
    const float* bk   = (const float*)d_in[6];
    const float* wv   = (const float*)d_in[7];
    const float* bv   = (const float*)d_in[8];
    const float* wo   = (const float*)d_in[9];
    const float* bo   = (const float*)d_in[10];

    cudaFuncSetAttribute(qkv_tc,  cudaFuncAttributeMaxDynamicSharedMemorySize, GEMM_SMEM);
    cudaFuncSetAttribute(out_tc,  cudaFuncAttributeMaxDynamicSharedMemorySize, GEMM_SMEM);
    cudaFuncSetAttribute(attn_tc, cudaFuncAttributeMaxDynamicSharedMemorySize, ATTN_SMEM);

    round_w<<<1024, 256>>>(wq, wk, wv, wo);
    pe_kernel<<<512, 256>>>();
    ln_kernel<<<BT, 256>>>(x, ln_g, ln_b);
    qkv_tc<<<dim3(64, 12), 256, GEMM_SMEM>>>(bq, bk, bv);
    attn_tc<<<dim3(32, 8, 4), 128, ATTN_SMEM>>>();
    out_tc<<<dim3(64, 4), 256, GEMM_SMEM>>>(bo, (float*)d_out);
}

// round 11
// speedup vs baseline: 1.5644x; 1.1312x over previous
#include <cuda_runtime.h>
#include <cstdint>
#include <math.h>

#define D_MODEL 512
#define N_HEADS 8
#define DK      64
#define BATCH   4
#define SEQ     2048
#define BT      (BATCH * SEQ)   // 8192
#define LN_EPS  1e-5f
#define PE_C    0.14391157f     // ln(10000)/64
#define QSCALE  0.18033688f     // 0.125 * log2(e)

// ---------------- scratch (device globals; no allocation allowed) -----------
__device__ float g_normed[BT * D_MODEL];   // tf32-rounded LN output
__device__ float g_q[BT * D_MODEL];        // [b][h][t][dk], pre-scaled by QSCALE, tf32-rounded
__device__ float g_k[BT * D_MODEL];        // [b][h][t][dk], +PE, tf32-rounded
__device__ float g_vt[BT * D_MODEL];       // [b][h][dk][t], tf32-rounded
__device__ float g_ctx[BT * D_MODEL];      // [b][t][h*dk], tf32-rounded
__device__ float g_wr[4 * D_MODEL * D_MODEL];  // rounded wq,wk,wv,wo
__device__ float g_pe[SEQ * DK];           // sinusoidal PE table

// ---------------- PTX helpers ------------------------------------------------
__device__ __forceinline__ uint32_t smem_u32(const void* p) {
    return (uint32_t)__cvta_generic_to_shared((void*)p);
}
__device__ __forceinline__ uint32_t f2tf(float x) {
    uint32_t r; asm("cvt.rna.tf32.f32 %0, %1;" : "=r"(r) : "f"(x)); return r;
}
__device__ __forceinline__ float f2tff(float x) { return __uint_as_float(f2tf(x)); }
__device__ __forceinline__ float ex2(float x) {
    float r; asm("ex2.approx.ftz.f32 %0, %1;" : "=f"(r) : "f"(x)); return r;
}

#define CP16(dst, src) \
    asm volatile("cp.async.cg.shared.global [%0], [%1], 16;" :: "r"(dst), "l"(src))
#define CP_COMMIT() asm volatile("cp.async.commit_group;" ::: "memory")
#define CP_WAIT1()  asm volatile("cp.async.wait_group 1;" ::: "memory")
#define CP_WAIT0()  asm volatile("cp.async.wait_group 0;" ::: "memory")

#define LDSM4(r0, r1, r2, r3, addr) \
    asm volatile("ldmatrix.sync.aligned.m8n8.x4.shared.b16 {%0,%1,%2,%3}, [%4];" \
        : "=r"(r0), "=r"(r1), "=r"(r2), "=r"(r3) : "r"(addr))

#define STS64(addr, a, b) \
    asm volatile("st.shared.v2.b32 [%0], {%1,%2};" :: "r"(addr), "r"(a), "r"(b))

// C (f32x4) += A(tf32 m16k8) * B(tf32 k8n8)
#define MMA_TF32(c, a, b) \
    asm volatile("mma.sync.aligned.m16n8k8.row.col.f32.tf32.tf32.f32 " \
        "{%0,%1,%2,%3}, {%4,%5,%6,%7}, {%8,%9}, {%0,%1,%2,%3};" \
        : "+f"((c)[0]), "+f"((c)[1]), "+f"((c)[2]), "+f"((c)[3]) \
        : "r"((a)[0]), "r"((a)[1]), "r"((a)[2]), "r"((a)[3]), \
          "r"((b)[0]), "r"((b)[1]))

// ---------------- weight rounding + PE table prep ----------------------------
__global__ void round_w(const float* __restrict__ wq, const float* __restrict__ wk,
                        const float* __restrict__ wv, const float* __restrict__ wo) {
    int i = blockIdx.x * 256 + threadIdx.x;       // 262144 per matrix
    g_wr[i]              = f2tff(wq[i]);
    g_wr[262144 + i]     = f2tff(wk[i]);
    g_wr[2 * 262144 + i] = f2tff(wv[i]);
    g_wr[3 * 262144 + i] = f2tff(wo[i]);
}

__global__ void pe_kernel() {
    int i = blockIdx.x * 256 + threadIdx.x;       // SEQ*DK = 131072
    int t = i >> 6, d = i & 63;
    float f = expf(-PE_C * (float)(d & ~1));
    float ang = (float)t * f;
    g_pe[i] = (d & 1) ? cosf(ang) : sinf(ang);
}

// ---------------- LayerNorm (rounds output to tf32) --------------------------
__global__ void ln_kernel(const float* __restrict__ x,
                          const float* __restrict__ gamma,
                          const float* __restrict__ beta) {
    int row = blockIdx.x;
    int tid = threadIdx.x;            // 256 threads
    const float* xr = x + (size_t)row * D_MODEL;
    float v0 = xr[tid];
    float v1 = xr[tid + 256];
    float s  = v0 + v1;
    float sq = v0 * v0 + v1 * v1;
    #pragma unroll
    for (int o = 16; o > 0; o >>= 1) {
        s  += __shfl_xor_sync(0xffffffffu, s,  o);
        sq += __shfl_xor_sync(0xffffffffu, sq, o);
    }
    __shared__ float ss[8], ssq[8];
    __shared__ float s_mu, s_rstd;
    int w = tid >> 5, l = tid & 31;
    if (l == 0) { ss[w] = s; ssq[w] = sq; }
    __syncthreads();
    if (tid == 0) {
        float S = 0.f, SQ = 0.f;
        #pragma unroll
        for (int i = 0; i < 8; i++) { S += ss[i]; SQ += ssq[i]; }
        float mu = S * (1.0f / D_MODEL);
        float var = SQ * (1.0f / D_MODEL) - mu * mu;
        s_mu = mu;
        s_rstd = rsqrtf(var + LN_EPS);
    }
    __syncthreads();
    float mu = s_mu, rs = s_rstd;
    float* out = g_normed + (size_t)row * D_MODEL;
    out[tid]       = f2tff((v0 - mu) * rs * gamma[tid]       + beta[tid]);
    out[tid + 256] = f2tff((v1 - mu) * rs * gamma[tid + 256] + beta[tid + 256]);
}

// ---------------- shared 128x128x512 tf32 mainloop ---------------------------
// 256 threads, 8 warps (2m x 4n), warp tile 64x32, BK=32, double-buffered.
// smem: A [2][128][32] swizzled @0 (32KB), B same @32768. Total 65536.
#define GEMM_SMEM 65536

__device__ __forceinline__ void gemm_mainloop(
    const float* __restrict__ A, const float* __restrict__ B,
    int m0, int n0, char* smem, float acc[4][4][4])
{
    uint32_t sA = smem_u32(smem), sB = sA + 32768;
    int tid = threadIdx.x, wid = tid >> 5, lane = tid & 31;
    int wm = (wid >> 2) * 64, wn = (wid & 3) * 32;

    #pragma unroll
    for (int i = 0; i < 4; i++) {
        int id = tid + i * 256, r = id >> 3, c = id & 7;
        uint32_t off = (uint32_t)((r * 8 + (c ^ (r & 7))) * 16);
        CP16(sA + off, A + (size_t)(m0 + r) * 512 + c * 4);
        CP16(sB + off, B + (size_t)(n0 + r) * 512 + c * 4);
    }
    CP_COMMIT();

    for (int itk = 0; itk < 16; itk++) {
        int buf = itk & 1;
        if (itk < 15) {
            int k0 = (itk + 1) * 32, nb = (itk + 1) & 1;
            #pragma unroll
            for (int i = 0; i < 4; i++) {
                int id = tid + i * 256, r = id >> 3, c = id & 7;
                uint32_t off = (uint32_t)(nb * 16384 + (r * 8 + (c ^ (r & 7))) * 16);
                CP16(sA + off, A + (size_t)(m0 + r) * 512 + k0 + c * 4);
                CP16(sB + off, B + (size_t)(n0 + r) * 512 + k0 + c * 4);
            }
            CP_COMMIT();
            CP_WAIT1();
        } else {
            CP_WAIT0();
        }
        __syncthreads();

        uint32_t ab = sA + buf * 16384, bb = sB + buf * 16384;
        #pragma unroll
        for (int ks = 0; ks < 4; ks++) {
            uint32_t af[4][4];
            #pragma unroll
            for (int mi = 0; mi < 4; mi++) {
                int r = wm + mi * 16 + (lane & 15);
                int c = 2 * ks + (lane >> 4);
                LDSM4(af[mi][0], af[mi][1], af[mi][2], af[mi][3],
                      ab + (r * 8 + (c ^ (r & 7))) * 16);
            }
            uint32_t bf[4][2];
            #pragma unroll
            for (int nj2 = 0; nj2 < 2; nj2++) {
                int r = wn + nj2 * 16 + (lane & 7) + ((lane >> 4) << 3);
                int c = 2 * ks + ((lane >> 3) & 1);
                uint32_t t0, t1, t2, t3;
                LDSM4(t0, t1, t2, t3, bb + (r * 8 + (c ^ (r & 7))) * 16);
                bf[nj2 * 2][0] = t0; bf[nj2 * 2][1] = t1;
                bf[nj2 * 2 + 1][0] = t2; bf[nj2 * 2 + 1][1] = t3;
            }
            #pragma unroll
            for (int mi = 0; mi < 4; mi++)
                #pragma unroll
                for (int nj = 0; nj < 4; nj++)
                    MMA_TF32(acc[mi][nj], af[mi], bf[nj]);
        }
        __syncthreads();
    }
}

// ---------------- QKV projection (+bias, +PE on K, head scatter) -------------
__global__ __launch_bounds__(256) void qkv_tc(
    const float* __restrict__ bq, const float* __restrict__ bk,
    const float* __restrict__ bv)
{
    extern __shared__ char smem[];
    int tid = threadIdx.x, wid = tid >> 5, lane = tid & 31;
    int m0 = blockIdx.x * 128;
    int ng = blockIdx.y * 128;
    int wsel = ng >> 9, n0 = ng & 511;

    float acc[4][4][4];
    #pragma unroll
    for (int a = 0; a < 4; a++)
        #pragma unroll
        for (int b = 0; b < 4; b++)
            #pragma unroll
            for (int c = 0; c < 4; c++) acc[a][b][c] = 0.f;

    gemm_mainloop(g_normed, g_wr + (size_t)wsel * 262144, m0, n0, smem, acc);

    const float* bias = (wsel == 0) ? bq : (wsel == 1) ? bk : bv;
    int wm = (wid >> 2) * 64, wn = (wid & 3) * 32;
    #pragma unroll
    for (int mi = 0; mi < 4; mi++) {
        #pragma unroll
        for (int rr = 0; rr < 2; rr++) {
            int m = m0 + wm + mi * 16 + (lane >> 2) + rr * 8;
            int b = m >> 11, t = m & (SEQ - 1);
            #pragma unroll
            for (int nj = 0; nj < 4; nj++) {
                #pragma unroll
                for (int cc = 0; cc < 2; cc++) {
                    int n = n0 + wn + nj * 8 + (lane & 3) * 2 + cc;
                    float v = acc[mi][nj][rr * 2 + cc] + bias[n];
                    int h = n >> 6, d = n & 63;
                    size_t bh = (size_t)(b * N_HEADS + h);
                    if (wsel == 0) {
                        g_q[(bh * SEQ + t) * DK + d] = f2tff(v * QSCALE);
                    } else if (wsel == 1) {
                        v += g_pe[t * DK + d];
                        g_k[(bh * SEQ + t) * DK + d] = f2tff(v);
                    } else {
                        g_vt[(bh * DK + d) * SEQ + t] = f2tff(v);
                    }
                }
            }
        }
    }
}

// ---------------- output projection ------------------------------------------
__global__ __launch_bounds__(256) void out_tc(const float* __restrict__ bo,
                                              float* __restrict__ out)
{
    extern __shared__ char smem[];
    int tid = threadIdx.x, wid = tid >> 5, lane = tid & 31;
    int m0 = blockIdx.x * 128;
    int n0 = blockIdx.y * 128;

    float acc[4][4][4];
    #pragma unroll
    for (int a = 0; a < 4; a++)
        #pragma unroll
        for (int b = 0; b < 4; b++)
            #pragma unroll
            for (int c = 0; c < 4; c++) acc[a][b][c] = 0.f;

    gemm_mainloop(g_ctx, g_wr + 3 * 262144, m0, n0, smem, acc);

    int wm = (wid >> 2) * 64, wn = (wid & 3) * 32;
    #pragma unroll
    for (int mi = 0; mi < 4; mi++) {
        #pragma unroll
        for (int rr = 0; rr < 2; rr++) {
            int m = m0 + wm + mi * 16 + (lane >> 2) + rr * 8;
            #pragma unroll
            for (int nj = 0; nj < 4; nj++) {
                int n = n0 + wn + nj * 8 + (lane & 3) * 2;
                float2 v;
                v.x = acc[mi][nj][rr * 2]     + bo[n];
                v.y = acc[mi][nj][rr * 2 + 1] + bo[n + 1];
                *(float2*)(out + (size_t)m * 512 + n) = v;
            }
        }
    }
}

// ---------------- flash attention (tf32 mma.sync) ----------------------------
// CTA: 64 q-rows, 128 threads (4 warps each owning m16). K/V tile = 64, db.
// Q fragments held in registers (32 regs) after one-time ldmatrix.
// Softmax runs in base-2 domain (Q pre-scaled by 0.125*log2e at qkv epilogue).
// smem: Qs[64][64]@0 16KB, Ks[2][64][64]@16384 32KB, Vts[2][64][64]@49152 32KB,
//       Ps[64][64]@81920 16KB. Total 98304 B -> 2 CTAs/SM by smem, regs free.
#define ATTN_SMEM 98304

__global__ __launch_bounds__(128) void attn_tc() {
    extern __shared__ char smem[];
    uint32_t sQ = smem_u32(smem);
    uint32_t sK = sQ + 16384;
    uint32_t sV = sQ + 49152;
    uint32_t sP = sQ + 81920;
    int tid = threadIdx.x, wid = tid >> 5, lane = tid & 31;
    int bh = blockIdx.z * N_HEADS + blockIdx.y;
    int q0 = blockIdx.x * 64;
    const float* Qb  = g_q  + (size_t)bh * SEQ * DK;
    const float* Kb  = g_k  + (size_t)bh * SEQ * DK;
    const float* Vtb = g_vt + (size_t)bh * DK * SEQ;

    // stage Q [64 x 64] : 1024 chunks of 16B over 128 threads
    #pragma unroll
    for (int i = 0; i < 8; i++) {
        int id = tid + i * 128, r = id >> 4, c = id & 15;
        CP16(sQ + (r * 16 + (c ^ (r & 7))) * 16, Qb + (size_t)(q0 + r) * DK + c * 4);
    }
    CP_COMMIT();
    // stage K/V tile 0
    #pragma unroll
    for (int i = 0; i < 8; i++) {
        int id = tid + i * 128, r = id >> 4, c = id & 15;
        uint32_t off = (r * 16 + (c ^ (r & 7))) * 16;
        CP16(sK + off, Kb + (size_t)r * DK + c * 4);
        CP16(sV + off, Vtb + (size_t)r * SEQ + c * 4);
    }
    CP_COMMIT();

    // Q fragments resident in registers: one-time ldmatrix after Q lands.
    uint32_t qf[8][4];
    CP_WAIT1();            // Q group complete (K/V group may still be in flight)
    __syncthreads();
    #pragma unroll
    for (int ks = 0; ks < 8; ks++) {
        int r = wid * 16 + (lane & 15);
        int c = 2 * ks + (lane >> 4);
        LDSM4(qf[ks][0], qf[ks][1], qf[ks][2], qf[ks][3],
              sQ + (r * 16 + (c ^ (r & 7))) * 16);
    }

    float accO[8][4];
    #pragma unroll
    for (int nj = 0; nj < 8; nj++)
        #pragma unroll
        for (int k = 0; k < 4; k++) accO[nj][k] = 0.f;
    float mrun0 = -1e30f, mrun1 = -1e30f, l0 = 0.f, l1 = 0.f;

    for (int it = 0; it < 32; it++) {
        int buf = it & 1;
        if (it < 31) {
            int s0 = (it + 1) * 64, nb = (it + 1) & 1;
            #pragma unroll
            for (int i = 0; i < 8; i++) {
                int id = tid + i * 128, r = id >> 4, c = id & 15;
                uint32_t off = nb * 16384 + (r * 16 + (c ^ (r & 7))) * 16;
                CP16(sK + off, Kb + (size_t)(s0 + r) * DK + c * 4);
                CP16(sV + off, Vtb + (size_t)r * SEQ + s0 + c * 4);
            }
            CP_COMMIT();
            CP_WAIT1();
        } else {
            CP_WAIT0();
        }
        __syncthreads();

        uint32_t kb = sK + buf * 16384, vb = sV + buf * 16384;

        // ---- S' = (QSCALE*Q) @ K^T : per-warp m16 x n64, k=64 (8 ksteps) ----
        float s[8][4];
        #pragma unroll
        for (int nj = 0; nj < 8; nj++)
            #pragma unroll
            for (int k = 0; k < 4; k++) s[nj][k] = 0.f;
        #pragma unroll
        for (int ks = 0; ks < 8; ks++) {
            #pragma unroll
            for (int nj2 = 0; nj2 < 4; nj2++) {
                int r = nj2 * 16 + (lane & 7) + ((lane >> 4) << 3);
                int c = 2 * ks + ((lane >> 3) & 1);
                uint32_t t0, t1, t2, t3;
                LDSM4(t0, t1, t2, t3, kb + (r * 16 + (c ^ (r & 7))) * 16);
                uint32_t b0[2] = {t0, t1}, b1[2] = {t2, t3};
                MMA_TF32(s[nj2 * 2], qf[ks], b0);
                MMA_TF32(s[nj2 * 2 + 1], qf[ks], b1);
            }
        }

        // ---- online softmax in base-2 domain (rows g and g+8 per lane) ----
        float ml0 = -1e30f, ml1 = -1e30f;
        #pragma unroll
        for (int nj = 0; nj < 8; nj++) {
            ml0 = fmaxf(ml0, fmaxf(s[nj][0], s[nj][1]));
            ml1 = fmaxf(ml1, fmaxf(s[nj][2], s[nj][3]));
        }
        ml0 = fmaxf(ml0, __shfl_xor_sync(0xffffffffu, ml0, 1));
        ml0 = fmaxf(ml0, __shfl_xor_sync(0xffffffffu, ml0, 2));
        ml1 = fmaxf(ml1, __shfl_xor_sync(0xffffffffu, ml1, 1));
        ml1 = fmaxf(ml1, __shfl_xor_sync(0xffffffffu, ml1, 2));
        float mn0 = fmaxf(mrun0, ml0), mn1 = fmaxf(mrun1, ml1);
        float al0 = ex2(mrun0 - mn0), al1 = ex2(mrun1 - mn1);
        float rs0 = 0.f, rs1 = 0.f;
        #pragma unroll
        for (int nj = 0; nj < 8; nj++) {
            s[nj][0] = ex2(s[nj][0] - mn0);
            s[nj][1] = ex2(s[nj][1] - mn0);
            s[nj][2] = ex2(s[nj][2] - mn1);
            s[nj][3] = ex2(s[nj][3] - mn1);
            rs0 += s[nj][0] + s[nj][1];
            rs1 += s[nj][2] + s[nj][3];
        }
        rs0 += __shfl_xor_sync(0xffffffffu, rs0, 1);
        rs0 += __shfl_xor_sync(0xffffffffu, rs0, 2);
        rs1 += __shfl_xor_sync(0xffffffffu, rs1, 1);
        rs1 += __shfl_xor_sync(0xffffffffu, rs1, 2);
        l0 = l0 * al0 + rs0;  l1 = l1 * al1 + rs1;
        mrun0 = mn0;          mrun1 = mn1;
        #pragma unroll
        for (int nj = 0; nj < 8; nj++) {
            accO[nj][0] *= al0; accO[nj][1] *= al0;
            accO[nj][2] *= al1; accO[nj][3] *= al1;
        }

        // ---- store P (tf32-rounded) to smem in A-operand layout ----
        {
            int r0 = wid * 16 + (lane >> 2), r1 = r0 + 8;
            int off8 = (lane & 1) * 8;
            #pragma unroll
            for (int nj = 0; nj < 8; nj++) {
                int col = nj * 8 + (lane & 3) * 2;
                int ch = col >> 2;
                STS64(sP + (r0 * 16 + (ch ^ (r0 & 7))) * 16 + off8,
                      f2tf(s[nj][0]), f2tf(s[nj][1]));
                STS64(sP + (r1 * 16 + (ch ^ (r1 & 7))) * 16 + off8,
                      f2tf(s[nj][2]), f2tf(s[nj][3]));
            }
        }
        __syncwarp();

        // ---- O += P @ V : per-warp m16 x n64(d), k=64(s) ----
        #pragma unroll
        for (int ks = 0; ks < 8; ks++) {
            uint32_t af[4];
            {
                int r = wid * 16 + (lane & 15);
                int c = 2 * ks + (lane >> 4);
                LDSM4(af[0], af[1], af[2], af[3], sP + (r * 16 + (c ^ (r & 7))) * 16);
            }
            #pragma unroll
            for (int nj2 = 0; nj2 < 4; nj2++) {
                int r = nj2 * 16 + (lane & 7) + ((lane >> 4) << 3);
                int c = 2 * ks + ((lane >> 3) & 1);
                uint32_t t0, t1, t2, t3;
                LDSM4(t0, t1, t2, t3, vb + (r * 16 + (c ^ (r & 7))) * 16);
                uint32_t b0[2] = {t0, t1}, b1[2] = {t2, t3};
                MMA_TF32(accO[nj2 * 2], af, b0);
                MMA_TF32(accO[nj2 * 2 + 1], af, b1);
            }
        }
        __syncthreads();
    }

    // ---- epilogue: normalize, round, write to g_ctx ----
    float inv0 = 1.0f / l0, inv1 = 1.0f / l1;
    int t0 = q0 + wid * 16 + (lane >> 2), t1 = t0 + 8;
    float* dst = g_ctx + (size_t)blockIdx.z * SEQ * D_MODEL + (size_t)blockIdx.y * DK;
    #pragma unroll
    for (int nj = 0; nj < 8; nj++) {
        int col = nj * 8 + (lane & 3) * 2;
        float2 v0, v1;
        v0.x = f2tff(accO[nj][0] * inv0); v0.y = f2tff(accO[nj][1] * inv0);
        v1.x = f2tff(accO[nj][2] * inv1); v1.y = f2tff(accO[nj][3] * inv1);
        *(float2*)(dst + (size_t)t0 * D_MODEL + col) = v0;
        *(float2*)(dst + (size_t)t1 * D_MODEL + col) = v1;
    }
}

// ---------------- launch -----------------------------------------------------
extern "C" void kernel_launch(void* const* d_in, const int* in_sizes, int n_in,
                              void* d_out, int out_size) {
    const float* x    = (const float*)d_in[0];
    const float* ln_g = (const float*)d_in[1];
    const float* ln_b = (const float*)d_in[2];
    const float* wq   = (const float*)d_in[3];
    const float* bq   = (const float*)d_in[4];
    const float* wk   = (const float*)d_in[5];
    const float* bk   = (const float*)d_in[6];
    const float* wv   = (const float*)d_in[7];
    const float* bv   = (const float*)d_in[8];
    const float* wo   = (const float*)d_in[9];
    const float* bo   = (const float*)d_in[10];

    cudaFuncSetAttribute(qkv_tc,  cudaFuncAttributeMaxDynamicSharedMemorySize, GEMM_SMEM);
    cudaFuncSetAttribute(out_tc,  cudaFuncAttributeMaxDynamicSharedMemorySize, GEMM_SMEM);
    cudaFuncSetAttribute(attn_tc, cudaFuncAttributeMaxDynamicSharedMemorySize, ATTN_SMEM);

    round_w<<<1024, 256>>>(wq, wk, wv, wo);
    pe_kernel<<<512, 256>>>();
    ln_kernel<<<BT, 256>>>(x, ln_g, ln_b);
    qkv_tc<<<dim3(64, 12), 256, GEMM_SMEM>>>(bq, bk, bv);
    attn_tc<<<dim3(32, 8, 4), 128, ATTN_SMEM>>>();
    out_tc<<<dim3(64, 4), 256, GEMM_SMEM>>>(bo, (float*)d_out);
}

// round 12
// speedup vs baseline: 1.6668x; 1.0654x over previous
#include <cuda_runtime.h>
#include <cstdint>
#include <math.h>

#define D_MODEL 512
#define N_HEADS 8
#define DK      64
#define BATCH   4
#define SEQ     2048
#define BT      (BATCH * SEQ)   // 8192
#define LN_EPS  1e-5f
#define PE_C    0.14391157f     // ln(10000)/64
#define QSCALE  0.18033688f     // 0.125 * log2(e)

// ---------------- scratch (device globals; no allocation allowed) -----------
__device__ float g_normed[BT * D_MODEL];   // tf32-rounded LN output
__device__ float g_q[BT * D_MODEL];        // [b][h][t][dk], pre-scaled by QSCALE, tf32-rounded
__device__ float g_k[BT * D_MODEL];        // [b][h][t][dk], +PE, tf32-rounded
__device__ float g_vt[BT * D_MODEL];       // [b][h][dk][t], tf32-rounded
__device__ float g_ctx[BT * D_MODEL];      // [b][t][h*dk], tf32-rounded
__device__ float g_wr[4 * D_MODEL * D_MODEL];  // rounded wq,wk,wv,wo
__device__ float g_pe[SEQ * DK];           // sinusoidal PE table

// ---------------- PTX helpers ------------------------------------------------
__device__ __forceinline__ uint32_t smem_u32(const void* p) {
    return (uint32_t)__cvta_generic_to_shared((void*)p);
}
__device__ __forceinline__ uint32_t f2tf(float x) {
    uint32_t r; asm("cvt.rna.tf32.f32 %0, %1;" : "=r"(r) : "f"(x)); return r;
}
__device__ __forceinline__ float f2tff(float x) { return __uint_as_float(f2tf(x)); }
__device__ __forceinline__ float ex2(float x) {
    float r; asm("ex2.approx.ftz.f32 %0, %1;" : "=f"(r) : "f"(x)); return r;
}

#define CP16(dst, src) \
    asm volatile("cp.async.cg.shared.global [%0], [%1], 16;" :: "r"(dst), "l"(src))
#define CP_COMMIT() asm volatile("cp.async.commit_group;" ::: "memory")
#define CP_WAIT1()  asm volatile("cp.async.wait_group 1;" ::: "memory")
#define CP_WAIT0()  asm volatile("cp.async.wait_group 0;" ::: "memory")

#define LDSM4(r0, r1, r2, r3, addr) \
    asm volatile("ldmatrix.sync.aligned.m8n8.x4.shared.b16 {%0,%1,%2,%3}, [%4];" \
        : "=r"(r0), "=r"(r1), "=r"(r2), "=r"(r3) : "r"(addr))

#define STS64(addr, a, b) \
    asm volatile("st.shared.v2.b32 [%0], {%1,%2};" :: "r"(addr), "r"(a), "r"(b))

// C (f32x4) += A(tf32 m16k8) * B(tf32 k8n8)
#define MMA_TF32(c, a, b) \
    asm volatile("mma.sync.aligned.m16n8k8.row.col.f32.tf32.tf32.f32 " \
        "{%0,%1,%2,%3}, {%4,%5,%6,%7}, {%8,%9}, {%0,%1,%2,%3};" \
        : "+f"((c)[0]), "+f"((c)[1]), "+f"((c)[2]), "+f"((c)[3]) \
        : "r"((a)[0]), "r"((a)[1]), "r"((a)[2]), "r"((a)[3]), \
          "r"((b)[0]), "r"((b)[1]))

// ---------------- weight rounding + PE table prep ----------------------------
__global__ void round_w(const float* __restrict__ wq, const float* __restrict__ wk,
                        const float* __restrict__ wv, const float* __restrict__ wo) {
    int i = blockIdx.x * 256 + threadIdx.x;       // 262144 per matrix
    g_wr[i]              = f2tff(wq[i]);
    g_wr[262144 + i]     = f2tff(wk[i]);
    g_wr[2 * 262144 + i] = f2tff(wv[i]);
    g_wr[3 * 262144 + i] = f2tff(wo[i]);
}

__global__ void pe_kernel() {
    int i = blockIdx.x * 256 + threadIdx.x;       // SEQ*DK = 131072
    int t = i >> 6, d = i & 63;
    float f = expf(-PE_C * (float)(d & ~1));
    float ang = (float)t * f;
    g_pe[i] = (d & 1) ? cosf(ang) : sinf(ang);
}

// ---------------- LayerNorm (rounds output to tf32) --------------------------
__global__ void ln_kernel(const float* __restrict__ x,
                          const float* __restrict__ gamma,
                          const float* __restrict__ beta) {
    int row = blockIdx.x;
    int tid = threadIdx.x;            // 256 threads
    const float* xr = x + (size_t)row * D_MODEL;
    float v0 = xr[tid];
    float v1 = xr[tid + 256];
    float s  = v0 + v1;
    float sq = v0 * v0 + v1 * v1;
    #pragma unroll
    for (int o = 16; o > 0; o >>= 1) {
        s  += __shfl_xor_sync(0xffffffffu, s,  o);
        sq += __shfl_xor_sync(0xffffffffu, sq, o);
    }
    __shared__ float ss[8], ssq[8];
    __shared__ float s_mu, s_rstd;
    int w = tid >> 5, l = tid & 31;
    if (l == 0) { ss[w] = s; ssq[w] = sq; }
    __syncthreads();
    if (tid == 0) {
        float S = 0.f, SQ = 0.f;
        #pragma unroll
        for (int i = 0; i < 8; i++) { S += ss[i]; SQ += ssq[i]; }
        float mu = S * (1.0f / D_MODEL);
        float var = SQ * (1.0f / D_MODEL) - mu * mu;
        s_mu = mu;
        s_rstd = rsqrtf(var + LN_EPS);
    }
    __syncthreads();
    float mu = s_mu, rs = s_rstd;
    float* out = g_normed + (size_t)row * D_MODEL;
    out[tid]       = f2tff((v0 - mu) * rs * gamma[tid]       + beta[tid]);
    out[tid + 256] = f2tff((v1 - mu) * rs * gamma[tid + 256] + beta[tid + 256]);
}

// ---------------- shared 128x128x512 tf32 mainloop ---------------------------
// 256 threads, 8 warps (2m x 4n), warp tile 64x32, BK=32, double-buffered.
// smem: A [2][128][32] swizzled @0 (32KB), B same @32768. Total 65536.
#define GEMM_SMEM 65536

__device__ __forceinline__ void gemm_mainloop(
    const float* __restrict__ A, const float* __restrict__ B,
    int m0, int n0, char* smem, float acc[4][4][4])
{
    uint32_t sA = smem_u32(smem), sB = sA + 32768;
    int tid = threadIdx.x, wid = tid >> 5, lane = tid & 31;
    int wm = (wid >> 2) * 64, wn = (wid & 3) * 32;

    #pragma unroll
    for (int i = 0; i < 4; i++) {
        int id = tid + i * 256, r = id >> 3, c = id & 7;
        uint32_t off = (uint32_t)((r * 8 + (c ^ (r & 7))) * 16);
        CP16(sA + off, A + (size_t)(m0 + r) * 512 + c * 4);
        CP16(sB + off, B + (size_t)(n0 + r) * 512 + c * 4);
    }
    CP_COMMIT();

    for (int itk = 0; itk < 16; itk++) {
        int buf = itk & 1;
        if (itk < 15) {
            int k0 = (itk + 1) * 32, nb = (itk + 1) & 1;
            #pragma unroll
            for (int i = 0; i < 4; i++) {
                int id = tid + i * 256, r = id >> 3, c = id & 7;
                uint32_t off = (uint32_t)(nb * 16384 + (r * 8 + (c ^ (r & 7))) * 16);
                CP16(sA + off, A + (size_t)(m0 + r) * 512 + k0 + c * 4);
                CP16(sB + off, B + (size_t)(n0 + r) * 512 + k0 + c * 4);
            }
            CP_COMMIT();
            CP_WAIT1();
        } else {
            CP_WAIT0();
        }
        __syncthreads();

        uint32_t ab = sA + buf * 16384, bb = sB + buf * 16384;
        #pragma unroll
        for (int ks = 0; ks < 4; ks++) {
            uint32_t af[4][4];
            #pragma unroll
            for (int mi = 0; mi < 4; mi++) {
                int r = wm + mi * 16 + (lane & 15);
                int c = 2 * ks + (lane >> 4);
                LDSM4(af[mi][0], af[mi][1], af[mi][2], af[mi][3],
                      ab + (r * 8 + (c ^ (r & 7))) * 16);
            }
            uint32_t bf[4][2];
            #pragma unroll
            for (int nj2 = 0; nj2 < 2; nj2++) {
                int r = wn + nj2 * 16 + (lane & 7) + ((lane >> 4) << 3);
                int c = 2 * ks + ((lane >> 3) & 1);
                uint32_t t0, t1, t2, t3;
                LDSM4(t0, t1, t2, t3, bb + (r * 8 + (c ^ (r & 7))) * 16);
                bf[nj2 * 2][0] = t0; bf[nj2 * 2][1] = t1;
                bf[nj2 * 2 + 1][0] = t2; bf[nj2 * 2 + 1][1] = t3;
            }
            #pragma unroll
            for (int mi = 0; mi < 4; mi++)
                #pragma unroll
                for (int nj = 0; nj < 4; nj++)
                    MMA_TF32(acc[mi][nj], af[mi], bf[nj]);
        }
        __syncthreads();
    }
}

// ---------------- QKV projection (+bias, +PE on K, head scatter) -------------
__global__ __launch_bounds__(256) void qkv_tc(
    const float* __restrict__ bq, const float* __restrict__ bk,
    const float* __restrict__ bv)
{
    extern __shared__ char smem[];
    int tid = threadIdx.x, wid = tid >> 5, lane = tid & 31;
    int m0 = blockIdx.x * 128;
    int ng = blockIdx.y * 128;
    int wsel = ng >> 9, n0 = ng & 511;

    float acc[4][4][4];
    #pragma unroll
    for (int a = 0; a < 4; a++)
        #pragma unroll
        for (int b = 0; b < 4; b++)
            #pragma unroll
            for (int c = 0; c < 4; c++) acc[a][b][c] = 0.f;

    gemm_mainloop(g_normed, g_wr + (size_t)wsel * 262144, m0, n0, smem, acc);

    const float* bias = (wsel == 0) ? bq : (wsel == 1) ? bk : bv;
    int wm = (wid >> 2) * 64, wn = (wid & 3) * 32;
    #pragma unroll
    for (int mi = 0; mi < 4; mi++) {
        #pragma unroll
        for (int rr = 0; rr < 2; rr++) {
            int m = m0 + wm + mi * 16 + (lane >> 2) + rr * 8;
            int b = m >> 11, t = m & (SEQ - 1);
            #pragma unroll
            for (int nj = 0; nj < 4; nj++) {
                #pragma unroll
                for (int cc = 0; cc < 2; cc++) {
                    int n = n0 + wn + nj * 8 + (lane & 3) * 2 + cc;
                    float v = acc[mi][nj][rr * 2 + cc] + bias[n];
                    int h = n >> 6, d = n & 63;
                    size_t bh = (size_t)(b * N_HEADS + h);
                    if (wsel == 0) {
                        g_q[(bh * SEQ + t) * DK + d] = f2tff(v * QSCALE);
                    } else if (wsel == 1) {
                        v += g_pe[t * DK + d];
                        g_k[(bh * SEQ + t) * DK + d] = f2tff(v);
                    } else {
                        g_vt[(bh * DK + d) * SEQ + t] = f2tff(v);
                    }
                }
            }
        }
    }
}

// ---------------- output projection ------------------------------------------
__global__ __launch_bounds__(256) void out_tc(const float* __restrict__ bo,
                                              float* __restrict__ out)
{
    extern __shared__ char smem[];
    int tid = threadIdx.x, wid = tid >> 5, lane = tid & 31;
    int m0 = blockIdx.x * 128;
    int n0 = blockIdx.y * 128;

    float acc[4][4][4];
    #pragma unroll
    for (int a = 0; a < 4; a++)
        #pragma unroll
        for (int b = 0; b < 4; b++)
            #pragma unroll
            for (int c = 0; c < 4; c++) acc[a][b][c] = 0.f;

    gemm_mainloop(g_ctx, g_wr + 3 * 262144, m0, n0, smem, acc);

    int wm = (wid >> 2) * 64, wn = (wid & 3) * 32;
    #pragma unroll
    for (int mi = 0; mi < 4; mi++) {
        #pragma unroll
        for (int rr = 0; rr < 2; rr++) {
            int m = m0 + wm + mi * 16 + (lane >> 2) + rr * 8;
            #pragma unroll
            for (int nj = 0; nj < 4; nj++) {
                int n = n0 + wn + nj * 8 + (lane & 3) * 2;
                float2 v;
                v.x = acc[mi][nj][rr * 2]     + bo[n];
                v.y = acc[mi][nj][rr * 2 + 1] + bo[n + 1];
                *(float2*)(out + (size_t)m * 512 + n) = v;
            }
        }
    }
}

// ---------------- flash attention (tf32 mma.sync) ----------------------------
// CTA: 64 q-rows, 128 threads (4 warps each owning m16). K/V tile = 64,
// SINGLE buffered -> smem 64KB -> 3 CTAs/SM (12 warps, 3/SMSP).
// Q fragments in registers; base-2 softmax (Q pre-scaled by 0.125*log2e).
// smem: Qs[64][64]@0 16KB, Ks[64][64]@16384 16KB, Vts[64][64]@32768 16KB,
//       Ps[64][64]@49152 16KB. Total 65536 B.
#define ATTN_SMEM 65536

__global__ __launch_bounds__(128) void attn_tc() {
    extern __shared__ char smem[];
    uint32_t sQ = smem_u32(smem);
    uint32_t sK = sQ + 16384;
    uint32_t sV = sQ + 32768;
    uint32_t sP = sQ + 49152;
    int tid = threadIdx.x, wid = tid >> 5, lane = tid & 31;
    int bh = blockIdx.z * N_HEADS + blockIdx.y;
    int q0 = blockIdx.x * 64;
    const float* Qb  = g_q  + (size_t)bh * SEQ * DK;
    const float* Kb  = g_k  + (size_t)bh * SEQ * DK;
    const float* Vtb = g_vt + (size_t)bh * DK * SEQ;

    // stage Q [64 x 64] + K/V tile 0
    #pragma unroll
    for (int i = 0; i < 8; i++) {
        int id = tid + i * 128, r = id >> 4, c = id & 15;
        uint32_t off = (r * 16 + (c ^ (r & 7))) * 16;
        CP16(sQ + off, Qb + (size_t)(q0 + r) * DK + c * 4);
        CP16(sK + off, Kb + (size_t)r * DK + c * 4);
        CP16(sV + off, Vtb + (size_t)r * SEQ + c * 4);
    }
    CP_COMMIT();
    CP_WAIT0();
    __syncthreads();

    // Q fragments resident in registers: one-time ldmatrix.
    uint32_t qf[8][4];
    #pragma unroll
    for (int ks = 0; ks < 8; ks++) {
        int r = wid * 16 + (lane & 15);
        int c = 2 * ks + (lane >> 4);
        LDSM4(qf[ks][0], qf[ks][1], qf[ks][2], qf[ks][3],
              sQ + (r * 16 + (c ^ (r & 7))) * 16);
    }

    float accO[8][4];
    #pragma unroll
    for (int nj = 0; nj < 8; nj++)
        #pragma unroll
        for (int k = 0; k < 4; k++) accO[nj][k] = 0.f;
    float mrun0 = -1e30f, mrun1 = -1e30f, l0 = 0.f, l1 = 0.f;

    for (int it = 0; it < 32; it++) {
        // ---- S' = (QSCALE*Q) @ K^T : per-warp m16 x n64, k=64 (8 ksteps) ----
        float s[8][4];
        #pragma unroll
        for (int nj = 0; nj < 8; nj++)
            #pragma unroll
            for (int k = 0; k < 4; k++) s[nj][k] = 0.f;
        #pragma unroll
        for (int ks = 0; ks < 8; ks++) {
            #pragma unroll
            for (int nj2 = 0; nj2 < 4; nj2++) {
                int r = nj2 * 16 + (lane & 7) + ((lane >> 4) << 3);
                int c = 2 * ks + ((lane >> 3) & 1);
                uint32_t t0, t1, t2, t3;
                LDSM4(t0, t1, t2, t3, sK + (r * 16 + (c ^ (r & 7))) * 16);
                uint32_t b0[2] = {t0, t1}, b1[2] = {t2, t3};
                MMA_TF32(s[nj2 * 2], qf[ks], b0);
                MMA_TF32(s[nj2 * 2 + 1], qf[ks], b1);
            }
        }

        // ---- online softmax in base-2 domain (rows g and g+8 per lane) ----
        float ml0 = -1e30f, ml1 = -1e30f;
        #pragma unroll
        for (int nj = 0; nj < 8; nj++) {
            ml0 = fmaxf(ml0, fmaxf(s[nj][0], s[nj][1]));
            ml1 = fmaxf(ml1, fmaxf(s[nj][2], s[nj][3]));
        }
        ml0 = fmaxf(ml0, __shfl_xor_sync(0xffffffffu, ml0, 1));
        ml0 = fmaxf(ml0, __shfl_xor_sync(0xffffffffu, ml0, 2));
        ml1 = fmaxf(ml1, __shfl_xor_sync(0xffffffffu, ml1, 1));
        ml1 = fmaxf(ml1, __shfl_xor_sync(0xffffffffu, ml1, 2));
        float mn0 = fmaxf(mrun0, ml0), mn1 = fmaxf(mrun1, ml1);
        float al0 = ex2(mrun0 - mn0), al1 = ex2(mrun1 - mn1);
        float rs0 = 0.f, rs1 = 0.f;
        #pragma unroll
        for (int nj = 0; nj < 8; nj++) {
            s[nj][0] = ex2(s[nj][0] - mn0);
            s[nj][1] = ex2(s[nj][1] - mn0);
            s[nj][2] = ex2(s[nj][2] - mn1);
            s[nj][3] = ex2(s[nj][3] - mn1);
            rs0 += s[nj][0] + s[nj][1];
            rs1 += s[nj][2] + s[nj][3];
        }
        rs0 += __shfl_xor_sync(0xffffffffu, rs0, 1);
        rs0 += __shfl_xor_sync(0xffffffffu, rs0, 2);
        rs1 += __shfl_xor_sync(0xffffffffu, rs1, 1);
        rs1 += __shfl_xor_sync(0xffffffffu, rs1, 2);
        l0 = l0 * al0 + rs0;  l1 = l1 * al1 + rs1;
        mrun0 = mn0;          mrun1 = mn1;
        #pragma unroll
        for (int nj = 0; nj < 8; nj++) {
            accO[nj][0] *= al0; accO[nj][1] *= al0;
            accO[nj][2] *= al1; accO[nj][3] *= al1;
        }

        // ---- store P (tf32-rounded) to smem in A-operand layout ----
        {
            int r0 = wid * 16 + (lane >> 2), r1 = r0 + 8;
            int off8 = (lane & 1) * 8;
            #pragma unroll
            for (int nj = 0; nj < 8; nj++) {
                int col = nj * 8 + (lane & 3) * 2;
                int ch = col >> 2;
                STS64(sP + (r0 * 16 + (ch ^ (r0 & 7))) * 16 + off8,
                      f2tf(s[nj][0]), f2tf(s[nj][1]));
                STS64(sP + (r1 * 16 + (ch ^ (r1 & 7))) * 16 + off8,
                      f2tf(s[nj][2]), f2tf(s[nj][3]));
            }
        }
        __syncwarp();

        // ---- O += P @ V : per-warp m16 x n64(d), k=64(s) ----
        #pragma unroll
        for (int ks = 0; ks < 8; ks++) {
            uint32_t af[4];
            {
                int r = wid * 16 + (lane & 15);
                int c = 2 * ks + (lane >> 4);
                LDSM4(af[0], af[1], af[2], af[3], sP + (r * 16 + (c ^ (r & 7))) * 16);
            }
            #pragma unroll
            for (int nj2 = 0; nj2 < 4; nj2++) {
                int r = nj2 * 16 + (lane & 7) + ((lane >> 4) << 3);
                int c = 2 * ks + ((lane >> 3) & 1);
                uint32_t t0, t1, t2, t3;
                LDSM4(t0, t1, t2, t3, sV + (r * 16 + (c ^ (r & 7))) * 16);
                uint32_t b0[2] = {t0, t1}, b1[2] = {t2, t3};
                MMA_TF32(accO[nj2 * 2], af, b0);
                MMA_TF32(accO[nj2 * 2 + 1], af, b1);
            }
        }
        __syncthreads();   // all warps done reading sK/sV

        // ---- load next K/V tile into the (single) buffer ----
        if (it < 31) {
            int s0 = (it + 1) * 64;
            #pragma unroll
            for (int i = 0; i < 8; i++) {
                int id = tid + i * 128, r = id >> 4, c = id & 15;
                uint32_t off = (r * 16 + (c ^ (r & 7))) * 16;
                CP16(sK + off, Kb + (size_t)(s0 + r) * DK + c * 4);
                CP16(sV + off, Vtb + (size_t)r * SEQ + s0 + c * 4);
            }
            CP_COMMIT();
            CP_WAIT0();
            __syncthreads();   // new tile visible to all warps
        }
    }

    // ---- epilogue: normalize, round, write to g_ctx ----
    float inv0 = 1.0f / l0, inv1 = 1.0f / l1;
    int t0 = q0 + wid * 16 + (lane >> 2), t1 = t0 + 8;
    float* dst = g_ctx + (size_t)blockIdx.z * SEQ * D_MODEL + (size_t)blockIdx.y * DK;
    #pragma unroll
    for (int nj = 0; nj < 8; nj++) {
        int col = nj * 8 + (lane & 3) * 2;
        float2 v0, v1;
        v0.x = f2tff(accO[nj][0] * inv0); v0.y = f2tff(accO[nj][1] * inv0);
        v1.x = f2tff(accO[nj][2] * inv1); v1.y = f2tff(accO[nj][3] * inv1);
        *(float2*)(dst + (size_t)t0 * D_MODEL + col) = v0;
        *(float2*)(dst + (size_t)t1 * D_MODEL + col) = v1;
    }
}

// ---------------- launch -----------------------------------------------------
extern "C" void kernel_launch(void* const* d_in, const int* in_sizes, int n_in,
                              void* d_out, int out_size) {
    const float* x    = (const float*)d_in[0];
    const float* ln_g = (const float*)d_in[1];
    const float* ln_b = (const float*)d_in[2];
    const float* wq   = (const float*)d_in[3];
    const float* bq   = (const float*)d_in[4];
    const float* wk   = (const float*)d_in[5];
    const float* bk   = (const float*)d_in[6];
    const float* wv   = (const float*)d_in[7];
    const float* bv   = (const float*)d_in[8];
    const float* wo   = (const float*)d_in[9];
    const float* bo   = (const float*)d_in[10];

    cudaFuncSetAttribute(qkv_tc,  cudaFuncAttributeMaxDynamicSharedMemorySize, GEMM_SMEM);
    cudaFuncSetAttribute(out_tc,  cudaFuncAttributeMaxDynamicSharedMemorySize, GEMM_SMEM);
    cudaFuncSetAttribute(attn_tc, cudaFuncAttributeMaxDynamicSharedMemorySize, ATTN_SMEM);

    round_w<<<1024, 256>>>(wq, wk, wv, wo);
    pe_kernel<<<512, 256>>>();
    ln_kernel<<<BT, 256>>>(x, ln_g, ln_b);
    qkv_tc<<<dim3(64, 12), 256, GEMM_SMEM>>>(bq, bk, bv);
    attn_tc<<<dim3(32, 8, 4), 128, ATTN_SMEM>>>();
    out_tc<<<dim3(64, 4), 256, GEMM_SMEM>>>(bo, (float*)d_out);
}

// round 13
// speedup vs baseline: 1.6967x; 1.0180x over previous
#include <cuda_runtime.h>
#include <cstdint>
#include <math.h>

#define D_MODEL 512
#define N_HEADS 8
#define DK      64
#define BATCH   4
#define SEQ     2048
#define BT      (BATCH * SEQ)   // 8192
#define LN_EPS  1e-5f
#define PE_C    0.14391157f     // ln(10000)/64
#define QSCALE  0.18033688f     // 0.125 * log2(e)

// ---------------- scratch (device globals; no allocation allowed) -----------
__device__ float g_normed[BT * D_MODEL];   // tf32-rounded LN output
__device__ float g_q[BT * D_MODEL];        // [b][h][t][dk], pre-scaled by QSCALE, tf32-rounded
__device__ float g_k[BT * D_MODEL];        // [b][h][t][dk], +PE, tf32-rounded
__device__ float g_vt[BT * D_MODEL];       // [b][h][dk][t], tf32-rounded
__device__ float g_ctx[BT * D_MODEL];      // [b][t][h*dk], tf32-rounded
__device__ float g_wr[4 * D_MODEL * D_MODEL];  // rounded wq,wk,wv,wo
__device__ float g_pe[SEQ * DK];           // sinusoidal PE table

// ---------------- PTX helpers ------------------------------------------------
__device__ __forceinline__ uint32_t smem_u32(const void* p) {
    return (uint32_t)__cvta_generic_to_shared((void*)p);
}
__device__ __forceinline__ uint32_t f2tf(float x) {
    uint32_t r; asm("cvt.rna.tf32.f32 %0, %1;" : "=r"(r) : "f"(x)); return r;
}
__device__ __forceinline__ float f2tff(float x) { return __uint_as_float(f2tf(x)); }
__device__ __forceinline__ float ex2(float x) {
    float r; asm("ex2.approx.ftz.f32 %0, %1;" : "=f"(r) : "f"(x)); return r;
}

#define CP16(dst, src) \
    asm volatile("cp.async.cg.shared.global [%0], [%1], 16;" :: "r"(dst), "l"(src))
#define CP_COMMIT() asm volatile("cp.async.commit_group;" ::: "memory")
#define CP_WAIT1()  asm volatile("cp.async.wait_group 1;" ::: "memory")
#define CP_WAIT0()  asm volatile("cp.async.wait_group 0;" ::: "memory")

#define LDSM4(r0, r1, r2, r3, addr) \
    asm volatile("ldmatrix.sync.aligned.m8n8.x4.shared.b16 {%0,%1,%2,%3}, [%4];" \
        : "=r"(r0), "=r"(r1), "=r"(r2), "=r"(r3) : "r"(addr))

#define STS64(addr, a, b) \
    asm volatile("st.shared.v2.b32 [%0], {%1,%2};" :: "r"(addr), "r"(a), "r"(b))

// C (f32x4) += A(tf32 m16k8) * B(tf32 k8n8)
#define MMA_TF32(c, a, b) \
    asm volatile("mma.sync.aligned.m16n8k8.row.col.f32.tf32.tf32.f32 " \
        "{%0,%1,%2,%3}, {%4,%5,%6,%7}, {%8,%9}, {%0,%1,%2,%3};" \
        : "+f"((c)[0]), "+f"((c)[1]), "+f"((c)[2]), "+f"((c)[3]) \
        : "r"((a)[0]), "r"((a)[1]), "r"((a)[2]), "r"((a)[3]), \
          "r"((b)[0]), "r"((b)[1]))

// ---------------- weight rounding + PE table prep ----------------------------
__global__ void round_w(const float* __restrict__ wq, const float* __restrict__ wk,
                        const float* __restrict__ wv, const float* __restrict__ wo) {
    int i = blockIdx.x * 256 + threadIdx.x;       // 262144 per matrix
    g_wr[i]              = f2tff(wq[i]);
    g_wr[262144 + i]     = f2tff(wk[i]);
    g_wr[2 * 262144 + i] = f2tff(wv[i]);
    g_wr[3 * 262144 + i] = f2tff(wo[i]);
}

__global__ void pe_kernel() {
    int i = blockIdx.x * 256 + threadIdx.x;       // SEQ*DK = 131072
    int t = i >> 6, d = i & 63;
    float f = expf(-PE_C * (float)(d & ~1));
    float ang = (float)t * f;
    g_pe[i] = (d & 1) ? cosf(ang) : sinf(ang);
}

// ---------------- LayerNorm (rounds output to tf32) --------------------------
__global__ void ln_kernel(const float* __restrict__ x,
                          const float* __restrict__ gamma,
                          const float* __restrict__ beta) {
    int row = blockIdx.x;
    int tid = threadIdx.x;            // 256 threads
    const float* xr = x + (size_t)row * D_MODEL;
    float v0 = xr[tid];
    float v1 = xr[tid + 256];
    float s  = v0 + v1;
    float sq = v0 * v0 + v1 * v1;
    #pragma unroll
    for (int o = 16; o > 0; o >>= 1) {
        s  += __shfl_xor_sync(0xffffffffu, s,  o);
        sq += __shfl_xor_sync(0xffffffffu, sq, o);
    }
    __shared__ float ss[8], ssq[8];
    __shared__ float s_mu, s_rstd;
    int w = tid >> 5, l = tid & 31;
    if (l == 0) { ss[w] = s; ssq[w] = sq; }
    __syncthreads();
    if (tid == 0) {
        float S = 0.f, SQ = 0.f;
        #pragma unroll
        for (int i = 0; i < 8; i++) { S += ss[i]; SQ += ssq[i]; }
        float mu = S * (1.0f / D_MODEL);
        float var = SQ * (1.0f / D_MODEL) - mu * mu;
        s_mu = mu;
        s_rstd = rsqrtf(var + LN_EPS);
    }
    __syncthreads();
    float mu = s_mu, rs = s_rstd;
    float* out = g_normed + (size_t)row * D_MODEL;
    out[tid]       = f2tff((v0 - mu) * rs * gamma[tid]       + beta[tid]);
    out[tid + 256] = f2tff((v1 - mu) * rs * gamma[tid + 256] + beta[tid + 256]);
}

// ---------------- shared 128x128x512 tf32 mainloop ---------------------------
// 256 threads, 8 warps (2m x 4n), warp tile 64x32, BK=32, double-buffered.
// smem: A [2][128][32] swizzled @0 (32KB), B same @32768. Total 65536.
#define GEMM_SMEM 65536

__device__ __forceinline__ void gemm_mainloop(
    const float* __restrict__ A, const float* __restrict__ B,
    int m0, int n0, char* smem, float acc[4][4][4])
{
    uint32_t sA = smem_u32(smem), sB = sA + 32768;
    int tid = threadIdx.x, wid = tid >> 5, lane = tid & 31;
    int wm = (wid >> 2) * 64, wn = (wid & 3) * 32;

    #pragma unroll
    for (int i = 0; i < 4; i++) {
        int id = tid + i * 256, r = id >> 3, c = id & 7;
        uint32_t off = (uint32_t)((r * 8 + (c ^ (r & 7))) * 16);
        CP16(sA + off, A + (size_t)(m0 + r) * 512 + c * 4);
        CP16(sB + off, B + (size_t)(n0 + r) * 512 + c * 4);
    }
    CP_COMMIT();

    for (int itk = 0; itk < 16; itk++) {
        int buf = itk & 1;
        if (itk < 15) {
            int k0 = (itk + 1) * 32, nb = (itk + 1) & 1;
            #pragma unroll
            for (int i = 0; i < 4; i++) {
                int id = tid + i * 256, r = id >> 3, c = id & 7;
                uint32_t off = (uint32_t)(nb * 16384 + (r * 8 + (c ^ (r & 7))) * 16);
                CP16(sA + off, A + (size_t)(m0 + r) * 512 + k0 + c * 4);
                CP16(sB + off, B + (size_t)(n0 + r) * 512 + k0 + c * 4);
            }
            CP_COMMIT();
            CP_WAIT1();
        } else {
            CP_WAIT0();
        }
        __syncthreads();

        uint32_t ab = sA + buf * 16384, bb = sB + buf * 16384;
        #pragma unroll
        for (int ks = 0; ks < 4; ks++) {
            uint32_t af[4][4];
            #pragma unroll
            for (int mi = 0; mi < 4; mi++) {
                int r = wm + mi * 16 + (lane & 15);
                int c = 2 * ks + (lane >> 4);
                LDSM4(af[mi][0], af[mi][1], af[mi][2], af[mi][3],
                      ab + (r * 8 + (c ^ (r & 7))) * 16);
            }
            uint32_t bf[4][2];
            #pragma unroll
            for (int nj2 = 0; nj2 < 2; nj2++) {
                int r = wn + nj2 * 16 + (lane & 7) + ((lane >> 4) << 3);
                int c = 2 * ks + ((lane >> 3) & 1);
                uint32_t t0, t1, t2, t3;
                LDSM4(t0, t1, t2, t3, bb + (r * 8 + (c ^ (r & 7))) * 16);
                bf[nj2 * 2][0] = t0; bf[nj2 * 2][1] = t1;
                bf[nj2 * 2 + 1][0] = t2; bf[nj2 * 2 + 1][1] = t3;
            }
            #pragma unroll
            for (int mi = 0; mi < 4; mi++)
                #pragma unroll
                for (int nj = 0; nj < 4; nj++)
                    MMA_TF32(acc[mi][nj], af[mi], bf[nj]);
        }
        __syncthreads();
    }
}

// ---------------- QKV projection (+bias, +PE on K, head scatter) -------------
__global__ __launch_bounds__(256) void qkv_tc(
    const float* __restrict__ bq, const float* __restrict__ bk,
    const float* __restrict__ bv)
{
    extern __shared__ char smem[];
    int tid = threadIdx.x, wid = tid >> 5, lane = tid & 31;
    int m0 = blockIdx.x * 128;
    int ng = blockIdx.y * 128;
    int wsel = ng >> 9, n0 = ng & 511;

    float acc[4][4][4];
    #pragma unroll
    for (int a = 0; a < 4; a++)
        #pragma unroll
        for (int b = 0; b < 4; b++)
            #pragma unroll
            for (int c = 0; c < 4; c++) acc[a][b][c] = 0.f;

    gemm_mainloop(g_normed, g_wr + (size_t)wsel * 262144, m0, n0, smem, acc);

    const float* bias = (wsel == 0) ? bq : (wsel == 1) ? bk : bv;
    int wm = (wid >> 2) * 64, wn = (wid & 3) * 32;
    #pragma unroll
    for (int mi = 0; mi < 4; mi++) {
        #pragma unroll
        for (int rr = 0; rr < 2; rr++) {
            int m = m0 + wm + mi * 16 + (lane >> 2) + rr * 8;
            int b = m >> 11, t = m & (SEQ - 1);
            #pragma unroll
            for (int nj = 0; nj < 4; nj++) {
                #pragma unroll
                for (int cc = 0; cc < 2; cc++) {
                    int n = n0 + wn + nj * 8 + (lane & 3) * 2 + cc;
                    float v = acc[mi][nj][rr * 2 + cc] + bias[n];
                    int h = n >> 6, d = n & 63;
                    size_t bh = (size_t)(b * N_HEADS + h);
                    if (wsel == 0) {
                        g_q[(bh * SEQ + t) * DK + d] = f2tff(v * QSCALE);
                    } else if (wsel == 1) {
                        v += g_pe[t * DK + d];
                        g_k[(bh * SEQ + t) * DK + d] = f2tff(v);
                    } else {
                        g_vt[(bh * DK + d) * SEQ + t] = f2tff(v);
                    }
                }
            }
        }
    }
}

// ---------------- output projection ------------------------------------------
__global__ __launch_bounds__(256) void out_tc(const float* __restrict__ bo,
                                              float* __restrict__ out)
{
    extern __shared__ char smem[];
    int tid = threadIdx.x, wid = tid >> 5, lane = tid & 31;
    int m0 = blockIdx.x * 128;
    int n0 = blockIdx.y * 128;

    float acc[4][4][4];
    #pragma unroll
    for (int a = 0; a < 4; a++)
        #pragma unroll
        for (int b = 0; b < 4; b++)
            #pragma unroll
            for (int c = 0; c < 4; c++) acc[a][b][c] = 0.f;

    gemm_mainloop(g_ctx, g_wr + 3 * 262144, m0, n0, smem, acc);

    int wm = (wid >> 2) * 64, wn = (wid & 3) * 32;
    #pragma unroll
    for (int mi = 0; mi < 4; mi++) {
        #pragma unroll
        for (int rr = 0; rr < 2; rr++) {
            int m = m0 + wm + mi * 16 + (lane >> 2) + rr * 8;
            #pragma unroll
            for (int nj = 0; nj < 4; nj++) {
                int n = n0 + wn + nj * 8 + (lane & 3) * 2;
                float2 v;
                v.x = acc[mi][nj][rr * 2]     + bo[n];
                v.y = acc[mi][nj][rr * 2 + 1] + bo[n + 1];
                *(float2*)(out + (size_t)m * 512 + n) = v;
            }
        }
    }
}

// ---------------- flash attention (tf32 mma.sync) ----------------------------
// CTA: 64 q-rows, 128 threads (4 warps each owning m16). K/V tile = 64.
// Q staging buffer is reused for P after the one-time ldmatrix (both touch
// only warp-private rows -> same-warp ordering, no barrier needed).
// V double-buffered (prefetch issued at iter start, full iter of cover);
// K single-buffered (prefetch issued right after the post-S sync, covered by
// softmax+P+PV). One wait_group 0 + 2 syncthreads per iter.
// smem: QP@0 16KB, K@16384 16KB, V0@32768 16KB, V1@49152 16KB = 64KB
//       -> 3 CTAs/SM, regs unconstrained.
#define ATTN_SMEM 65536

__global__ __launch_bounds__(128) void attn_tc() {
    extern __shared__ char smem[];
    uint32_t sQP = smem_u32(smem);
    uint32_t sK  = sQP + 16384;
    uint32_t sV0 = sQP + 32768;
    int tid = threadIdx.x, wid = tid >> 5, lane = tid & 31;
    int bh = blockIdx.z * N_HEADS + blockIdx.y;
    int q0 = blockIdx.x * 64;
    const float* Qb  = g_q  + (size_t)bh * SEQ * DK;
    const float* Kb  = g_k  + (size_t)bh * SEQ * DK;
    const float* Vtb = g_vt + (size_t)bh * DK * SEQ;

    // stage Q + K tile 0 + V tile 0
    #pragma unroll
    for (int i = 0; i < 8; i++) {
        int id = tid + i * 128, r = id >> 4, c = id & 15;
        uint32_t off = (r * 16 + (c ^ (r & 7))) * 16;
        CP16(sQP + off, Qb + (size_t)(q0 + r) * DK + c * 4);
        CP16(sK  + off, Kb + (size_t)r * DK + c * 4);
        CP16(sV0 + off, Vtb + (size_t)r * SEQ + c * 4);
    }
    CP_COMMIT();
    CP_WAIT0();
    __syncthreads();

    // Q fragments resident in registers: one-time ldmatrix (warp-private rows).
    uint32_t qf[8][4];
    #pragma unroll
    for (int ks = 0; ks < 8; ks++) {
        int r = wid * 16 + (lane & 15);
        int c = 2 * ks + (lane >> 4);
        LDSM4(qf[ks][0], qf[ks][1], qf[ks][2], qf[ks][3],
              sQP + (r * 16 + (c ^ (r & 7))) * 16);
    }

    float accO[8][4];
    #pragma unroll
    for (int nj = 0; nj < 8; nj++)
        #pragma unroll
        for (int k = 0; k < 4; k++) accO[nj][k] = 0.f;
    float mrun0 = -1e30f, mrun1 = -1e30f, l0 = 0.f, l1 = 0.f;

    for (int it = 0; it < 32; it++) {
        uint32_t vb    = sV0 + (uint32_t)(it & 1) * 16384;
        uint32_t vbalt = sV0 + (uint32_t)(1 - (it & 1)) * 16384;
        int s0n = (it + 1) * 64;

        // ---- prefetch V(it+1) into the alternate buffer (covered by full iter)
        if (it < 31) {
            #pragma unroll
            for (int i = 0; i < 8; i++) {
                int id = tid + i * 128, r = id >> 4, c = id & 15;
                uint32_t off = (r * 16 + (c ^ (r & 7))) * 16;
                CP16(vbalt + off, Vtb + (size_t)r * SEQ + s0n + c * 4);
            }
            CP_COMMIT();
        }

        // ---- S' = (QSCALE*Q) @ K^T : per-warp m16 x n64, k=64 (8 ksteps) ----
        float s[8][4];
        #pragma unroll
        for (int nj = 0; nj < 8; nj++)
            #pragma unroll
            for (int k = 0; k < 4; k++) s[nj][k] = 0.f;
        #pragma unroll
        for (int ks = 0; ks < 8; ks++) {
            #pragma unroll
            for (int nj2 = 0; nj2 < 4; nj2++) {
                int r = nj2 * 16 + (lane & 7) + ((lane >> 4) << 3);
                int c = 2 * ks + ((lane >> 3) & 1);
                uint32_t t0, t1, t2, t3;
                LDSM4(t0, t1, t2, t3, sK + (r * 16 + (c ^ (r & 7))) * 16);
                uint32_t b0[2] = {t0, t1}, b1[2] = {t2, t3};
                MMA_TF32(s[nj2 * 2], qf[ks], b0);
                MMA_TF32(s[nj2 * 2 + 1], qf[ks], b1);
            }
        }
        __syncthreads();               // all warps done reading sK

        // ---- prefetch K(it+1) into sK (covered by softmax + P + PV) ----
        if (it < 31) {
            #pragma unroll
            for (int i = 0; i < 8; i++) {
                int id = tid + i * 128, r = id >> 4, c = id & 15;
                uint32_t off = (r * 16 + (c ^ (r & 7))) * 16;
                CP16(sK + off, Kb + (size_t)(s0n + r) * DK + c * 4);
            }
            CP_COMMIT();
        }

        // ---- online softmax in base-2 domain (rows g and g+8 per lane) ----
        float ml0 = -1e30f, ml1 = -1e30f;
        #pragma unroll
        for (int nj = 0; nj < 8; nj++) {
            ml0 = fmaxf(ml0, fmaxf(s[nj][0], s[nj][1]));
            ml1 = fmaxf(ml1, fmaxf(s[nj][2], s[nj][3]));
        }
        ml0 = fmaxf(ml0, __shfl_xor_sync(0xffffffffu, ml0, 1));
        ml0 = fmaxf(ml0, __shfl_xor_sync(0xffffffffu, ml0, 2));
        ml1 = fmaxf(ml1, __shfl_xor_sync(0xffffffffu, ml1, 1));
        ml1 = fmaxf(ml1, __shfl_xor_sync(0xffffffffu, ml1, 2));
        float mn0 = fmaxf(mrun0, ml0), mn1 = fmaxf(mrun1, ml1);
        float al0 = ex2(mrun0 - mn0), al1 = ex2(mrun1 - mn1);
        float rs0 = 0.f, rs1 = 0.f;
        #pragma unroll
        for (int nj = 0; nj < 8; nj++) {
            s[nj][0] = ex2(s[nj][0] - mn0);
            s[nj][1] = ex2(s[nj][1] - mn0);
            s[nj][2] = ex2(s[nj][2] - mn1);
            s[nj][3] = ex2(s[nj][3] - mn1);
            rs0 += s[nj][0] + s[nj][1];
            rs1 += s[nj][2] + s[nj][3];
        }
        rs0 += __shfl_xor_sync(0xffffffffu, rs0, 1);
        rs0 += __shfl_xor_sync(0xffffffffu, rs0, 2);
        rs1 += __shfl_xor_sync(0xffffffffu, rs1, 1);
        rs1 += __shfl_xor_sync(0xffffffffu, rs1, 2);
        l0 = l0 * al0 + rs0;  l1 = l1 * al1 + rs1;
        mrun0 = mn0;          mrun1 = mn1;
        #pragma unroll
        for (int nj = 0; nj < 8; nj++) {
            accO[nj][0] *= al0; accO[nj][1] *= al0;
            accO[nj][2] *= al1; accO[nj][3] *= al1;
        }

        // ---- store P (tf32-rounded) into QP buffer, A-operand layout ----
        {
            int r0 = wid * 16 + (lane >> 2), r1 = r0 + 8;
            int off8 = (lane & 1) * 8;
            #pragma unroll
            for (int nj = 0; nj < 8; nj++) {
                int col = nj * 8 + (lane & 3) * 2;
                int ch = col >> 2;
                STS64(sQP + (r0 * 16 + (ch ^ (r0 & 7))) * 16 + off8,
                      f2tf(s[nj][0]), f2tf(s[nj][1]));
                STS64(sQP + (r1 * 16 + (ch ^ (r1 & 7))) * 16 + off8,
                      f2tf(s[nj][2]), f2tf(s[nj][3]));
            }
        }
        __syncwarp();

        // ---- O += P @ V : per-warp m16 x n64(d), k=64(s) ----
        #pragma unroll
        for (int ks = 0; ks < 8; ks++) {
            uint32_t af[4];
            {
                int r = wid * 16 + (lane & 15);
                int c = 2 * ks + (lane >> 4);
                LDSM4(af[0], af[1], af[2], af[3], sQP + (r * 16 + (c ^ (r & 7))) * 16);
            }
            #pragma unroll
            for (int nj2 = 0; nj2 < 4; nj2++) {
                int r = nj2 * 16 + (lane & 7) + ((lane >> 4) << 3);
                int c = 2 * ks + ((lane >> 3) & 1);
                uint32_t t0, t1, t2, t3;
                LDSM4(t0, t1, t2, t3, vb + (r * 16 + (c ^ (r & 7))) * 16);
                uint32_t b0[2] = {t0, t1}, b1[2] = {t2, t3};
                MMA_TF32(accO[nj2 * 2], af, b0);
                MMA_TF32(accO[nj2 * 2 + 1], af, b1);
            }
        }

        // ---- wait for K(it+1)/V(it+1) and make them visible ----
        if (it < 31) {
            CP_WAIT0();
        }
        __syncthreads();
    }

    // ---- epilogue: normalize, round, write to g_ctx ----
    float inv0 = 1.0f / l0, inv1 = 1.0f / l1;
    int t0 = q0 + wid * 16 + (lane >> 2), t1 = t0 + 8;
    float* dst = g_ctx + (size_t)blockIdx.z * SEQ * D_MODEL + (size_t)blockIdx.y * DK;
    #pragma unroll
    for (int nj = 0; nj < 8; nj++) {
        int col = nj * 8 + (lane & 3) * 2;
        float2 v0, v1;
        v0.x = f2tff(accO[nj][0] * inv0); v0.y = f2tff(accO[nj][1] * inv0);
        v1.x = f2tff(accO[nj][2] * inv1); v1.y = f2tff(accO[nj][3] * inv1);
        *(float2*)(dst + (size_t)t0 * D_MODEL + col) = v0;
        *(float2*)(dst + (size_t)t1 * D_MODEL + col) = v1;
    }
}

// ---------------- launch -----------------------------------------------------
extern "C" void kernel_launch(void* const* d_in, const int* in_sizes, int n_in,
                              void* d_out, int out_size) {
    const float* x    = (const float*)d_in[0];
    const float* ln_g = (const float*)d_in[1];
    const float* ln_b = (const float*)d_in[2];
    const float* wq   = (const float*)d_in[3];
    const float* bq   = (const float*)d_in[4];
    const float* wk   = (const float*)d_in[5];
    const float* bk   = (const float*)d_in[6];
    const float* wv   = (const float*)d_in[7];
    const float* bv   = (const float*)d_in[8];
    const float* wo   = (const float*)d_in[9];
    const float* bo   = (const float*)d_in[10];

    cudaFuncSetAttribute(qkv_tc,  cudaFuncAttributeMaxDynamicSharedMemorySize, GEMM_SMEM);
    cudaFuncSetAttribute(out_tc,  cudaFuncAttributeMaxDynamicSharedMemorySize, GEMM_SMEM);
    cudaFuncSetAttribute(attn_tc, cudaFuncAttributeMaxDynamicSharedMemorySize, ATTN_SMEM);

    round_w<<<1024, 256>>>(wq, wk, wv, wo);
    pe_kernel<<<512, 256>>>();
    ln_kernel<<<BT, 256>>>(x, ln_g, ln_b);
    qkv_tc<<<dim3(64, 12), 256, GEMM_SMEM>>>(bq, bk, bv);
    attn_tc<<<dim3(32, 8, 4), 128, ATTN_SMEM>>>();
    out_tc<<<dim3(64, 4), 256, GEMM_SMEM>>>(bo, (float*)d_out);
}

// round 17
// speedup vs baseline: 1.7345x; 1.0222x over previous
#include <cuda_runtime.h>
#include <cstdint>
#include <math.h>

#define D_MODEL 512
#define N_HEADS 8
#define DK      64
#define BATCH   4
#define SEQ     2048
#define BT      (BATCH * SEQ)   // 8192
#define LN_EPS  1e-5f
#define PE_C    0.14391157f     // ln(10000)/64
#define QSCALE  0.18033688f     // 0.125 * log2(e)

// ---------------- scratch (device globals; no allocation allowed) -----------
__device__ float g_normed[BT * D_MODEL];   // tf32-rounded LN output
__device__ float g_q[BT * D_MODEL];        // [b][h][t][dk], pre-scaled by QSCALE, tf32-rounded
__device__ float g_k[BT * D_MODEL];        // [b][h][t][dk], +PE, tf32-rounded
__device__ float g_vt[BT * D_MODEL];       // [b][h][dk][t], tf32-rounded
__device__ float g_ctx[BT * D_MODEL];      // [b][t][h*dk], tf32-rounded
__device__ float g_wr[4 * D_MODEL * D_MODEL];  // rounded wq,wk,wv,wo
__device__ float g_pe[SEQ * DK];           // sinusoidal PE table

// ---------------- PTX helpers ------------------------------------------------
__device__ __forceinline__ uint32_t smem_u32(const void* p) {
    return (uint32_t)__cvta_generic_to_shared((void*)p);
}
__device__ __forceinline__ uint32_t f2tf(float x) {
    uint32_t r; asm("cvt.rna.tf32.f32 %0, %1;" : "=r"(r) : "f"(x)); return r;
}
__device__ __forceinline__ float f2tff(float x) { return __uint_as_float(f2tf(x)); }
__device__ __forceinline__ float ex2(float x) {
    float r; asm("ex2.approx.ftz.f32 %0, %1;" : "=f"(r) : "f"(x)); return r;
}

#define CP16(dst, src) \
    asm volatile("cp.async.cg.shared.global [%0], [%1], 16;" :: "r"(dst), "l"(src))
#define CP_COMMIT() asm volatile("cp.async.commit_group;" ::: "memory")
#define CP_WAIT1()  asm volatile("cp.async.wait_group 1;" ::: "memory")
#define CP_WAIT0()  asm volatile("cp.async.wait_group 0;" ::: "memory")

#define LDSM4(r0, r1, r2, r3, addr) \
    asm volatile("ldmatrix.sync.aligned.m8n8.x4.shared.b16 {%0,%1,%2,%3}, [%4];" \
        : "=r"(r0), "=r"(r1), "=r"(r2), "=r"(r3) : "r"(addr))

#define STS64(addr, a, b) \
    asm volatile("st.shared.v2.b32 [%0], {%1,%2};" :: "r"(addr), "r"(a), "r"(b))

// C (f32x4) += A(tf32 m16k8) * B(tf32 k8n8)
#define MMA_TF32(c, a, b) \
    asm volatile("mma.sync.aligned.m16n8k8.row.col.f32.tf32.tf32.f32 " \
        "{%0,%1,%2,%3}, {%4,%5,%6,%7}, {%8,%9}, {%0,%1,%2,%3};" \
        : "+f"((c)[0]), "+f"((c)[1]), "+f"((c)[2]), "+f"((c)[3]) \
        : "r"((a)[0]), "r"((a)[1]), "r"((a)[2]), "r"((a)[3]), \
          "r"((b)[0]), "r"((b)[1]))

// ---------------- prep: weight rounding + PE table (merged) ------------------
__global__ void prep_kernel(const float* __restrict__ wq, const float* __restrict__ wk,
                            const float* __restrict__ wv, const float* __restrict__ wo) {
    int i = blockIdx.x * 256 + threadIdx.x;       // 262144 per matrix
    g_wr[i]              = f2tff(wq[i]);
    g_wr[262144 + i]     = f2tff(wk[i]);
    g_wr[2 * 262144 + i] = f2tff(wv[i]);
    g_wr[3 * 262144 + i] = f2tff(wo[i]);
    if (i < SEQ * DK) {
        int t = i >> 6, d = i & 63;
        float f = expf(-PE_C * (float)(d & ~1));
        float ang = (float)t * f;
        g_pe[i] = (d & 1) ? cosf(ang) : sinf(ang);
    }
}

// ---------------- LayerNorm (float4, rounds output to tf32) ------------------
__global__ void ln_kernel(const float* __restrict__ x,
                          const float* __restrict__ gamma,
                          const float* __restrict__ beta) {
    int row = blockIdx.x;
    int tid = threadIdx.x;            // 128 threads, one float4 each
    const float4* xr = (const float4*)(x + (size_t)row * D_MODEL);
    float4 v = xr[tid];
    float s  = v.x + v.y + v.z + v.w;
    float sq = v.x * v.x + v.y * v.y + v.z * v.z + v.w * v.w;
    #pragma unroll
    for (int o = 16; o > 0; o >>= 1) {
        s  += __shfl_xor_sync(0xffffffffu, s,  o);
        sq += __shfl_xor_sync(0xffffffffu, sq, o);
    }
    __shared__ float ss[4], ssq[4];
    __shared__ float s_mu, s_rstd;
    int w = tid >> 5, l = tid & 31;
    if (l == 0) { ss[w] = s; ssq[w] = sq; }
    __syncthreads();
    if (tid == 0) {
        float S = ss[0] + ss[1] + ss[2] + ss[3];
        float SQ = ssq[0] + ssq[1] + ssq[2] + ssq[3];
        float mu = S * (1.0f / D_MODEL);
        float var = SQ * (1.0f / D_MODEL) - mu * mu;
        s_mu = mu;
        s_rstd = rsqrtf(var + LN_EPS);
    }
    __syncthreads();
    float mu = s_mu, rs = s_rstd;
    float4 g = ((const float4*)gamma)[tid];
    float4 b = ((const float4*)beta)[tid];
    float4 o;
    o.x = f2tff((v.x - mu) * rs * g.x + b.x);
    o.y = f2tff((v.y - mu) * rs * g.y + b.y);
    o.z = f2tff((v.z - mu) * rs * g.z + b.z);
    o.w = f2tff((v.w - mu) * rs * g.w + b.w);
    ((float4*)(g_normed + (size_t)row * D_MODEL))[tid] = o;
}

// ---------------- shared 128x128x512 tf32 mainloop ---------------------------
// 256 threads, 8 warps (2m x 4n), warp tile 64x32, BK=32, double-buffered.
// smem: A [2][128][32] swizzled @0 (32KB), B same @32768 (32KB).
// GEMM_SMEM = 67584 so the V epilogue can stage a [128][132] f32 tile.
#define GEMM_SMEM 67584

__device__ __forceinline__ void gemm_mainloop(
    const float* __restrict__ A, const float* __restrict__ B,
    int m0, int n0, char* smem, float acc[4][4][4])
{
    uint32_t sA = smem_u32(smem), sB = sA + 32768;
    int tid = threadIdx.x, wid = tid >> 5, lane = tid & 31;
    int wm = (wid >> 2) * 64, wn = (wid & 3) * 32;

    #pragma unroll
    for (int i = 0; i < 4; i++) {
        int id = tid + i * 256, r = id >> 3, c = id & 7;
        uint32_t off = (uint32_t)((r * 8 + (c ^ (r & 7))) * 16);
        CP16(sA + off, A + (size_t)(m0 + r) * 512 + c * 4);
        CP16(sB + off, B + (size_t)(n0 + r) * 512 + c * 4);
    }
    CP_COMMIT();

    for (int itk = 0; itk < 16; itk++) {
        int buf = itk & 1;
        if (itk < 15) {
            int k0 = (itk + 1) * 32, nb = (itk + 1) & 1;
            #pragma unroll
            for (int i = 0; i < 4; i++) {
                int id = tid + i * 256, r = id >> 3, c = id & 7;
                uint32_t off = (uint32_t)(nb * 16384 + (r * 8 + (c ^ (r & 7))) * 16);
                CP16(sA + off, A + (size_t)(m0 + r) * 512 + k0 + c * 4);
                CP16(sB + off, B + (size_t)(n0 + r) * 512 + k0 + c * 4);
            }
            CP_COMMIT();
            CP_WAIT1();
        } else {
            CP_WAIT0();
        }
        __syncthreads();

        uint32_t ab = sA + buf * 16384, bb = sB + buf * 16384;
        #pragma unroll
        for (int ks = 0; ks < 4; ks++) {
            uint32_t af[4][4];
            #pragma unroll
            for (int mi = 0; mi < 4; mi++) {
                int r = wm + mi * 16 + (lane & 15);
                int c = 2 * ks + (lane >> 4);
                LDSM4(af[mi][0], af[mi][1], af[mi][2], af[mi][3],
                      ab + (r * 8 + (c ^ (r & 7))) * 16);
            }
            uint32_t bf[4][2];
            #pragma unroll
            for (int nj2 = 0; nj2 < 2; nj2++) {
                int r = wn + nj2 * 16 + (lane & 7) + ((lane >> 4) << 3);
                int c = 2 * ks + ((lane >> 3) & 1);
                uint32_t t0, t1, t2, t3;
                LDSM4(t0, t1, t2, t3, bb + (r * 8 + (c ^ (r & 7))) * 16);
                bf[nj2 * 2][0] = t0; bf[nj2 * 2][1] = t1;
                bf[nj2 * 2 + 1][0] = t2; bf[nj2 * 2 + 1][1] = t3;
            }
            #pragma unroll
            for (int mi = 0; mi < 4; mi++)
                #pragma unroll
                for (int nj = 0; nj < 4; nj++)
                    MMA_TF32(acc[mi][nj], af[mi], bf[nj]);
        }
        __syncthreads();
    }
}

// ---------------- QKV projection (+bias, +PE on K, head scatter) -------------
__global__ __launch_bounds__(256) void qkv_tc(
    const float* __restrict__ bq, const float* __restrict__ bk,
    const float* __restrict__ bv)
{
    extern __shared__ char smem[];
    int tid = threadIdx.x, wid = tid >> 5, lane = tid & 31;
    int m0 = blockIdx.x * 128;
    int ng = blockIdx.y * 128;
    int wsel = ng >> 9, n0 = ng & 511;

    float acc[4][4][4];
    #pragma unroll
    for (int a = 0; a < 4; a++)
        #pragma unroll
        for (int b = 0; b < 4; b++)
            #pragma unroll
            for (int c = 0; c < 4; c++) acc[a][b][c] = 0.f;

    gemm_mainloop(g_normed, g_wr + (size_t)wsel * 262144, m0, n0, smem, acc);

    const float* bias = (wsel == 0) ? bq : (wsel == 1) ? bk : bv;
    int wm = (wid >> 2) * 64, wn = (wid & 3) * 32;

    if (wsel == 2) {
        // ---- V: stage [n][m] in smem (stride 132), then coalesced transpose ----
        float* sv = (float*)smem;
        #pragma unroll
        for (int mi = 0; mi < 4; mi++) {
            #pragma unroll
            for (int rr = 0; rr < 2; rr++) {
                int mloc = wm + mi * 16 + (lane >> 2) + rr * 8;
                #pragma unroll
                for (int nj = 0; nj < 4; nj++) {
                    #pragma unroll
                    for (int cc = 0; cc < 2; cc++) {
                        int nloc = wn + nj * 8 + (lane & 3) * 2 + cc;
                        sv[nloc * 132 + mloc] = acc[mi][nj][rr * 2 + cc] + bias[n0 + nloc];
                    }
                }
            }
        }
        __syncthreads();
        int b = m0 >> 11, t0 = m0 & (SEQ - 1);
        #pragma unroll
        for (int pass = 0; pass < 4; pass++) {
            int col = pass * 32 + (tid >> 3);          // 0..127
            int n = n0 + col; int h = n >> 6, d = n & 63;
            float* dst = g_vt + ((size_t)(b * N_HEADS + h) * DK + d) * SEQ + t0 + (tid & 7) * 16;
            const float* src = sv + col * 132 + (tid & 7) * 16;
            #pragma unroll
            for (int u = 0; u < 16; u += 4) {
                float4 o;
                o.x = f2tff(src[u]);     o.y = f2tff(src[u + 1]);
                o.z = f2tff(src[u + 2]); o.w = f2tff(src[u + 3]);
                *(float4*)(dst + u) = o;
            }
        }
    } else {
        // ---- Q / K: vectorized float2 stores ----
        float* dstbase = (wsel == 0) ? g_q : g_k;
        #pragma unroll
        for (int mi = 0; mi < 4; mi++) {
            #pragma unroll
            for (int rr = 0; rr < 2; rr++) {
                int m = m0 + wm + mi * 16 + (lane >> 2) + rr * 8;
                int b = m >> 11, t = m & (SEQ - 1);
                #pragma unroll
                for (int nj = 0; nj < 4; nj++) {
                    int n = n0 + wn + nj * 8 + (lane & 3) * 2;
                    int h = n >> 6, d = n & 63;
                    float v0 = acc[mi][nj][rr * 2]     + bias[n];
                    float v1 = acc[mi][nj][rr * 2 + 1] + bias[n + 1];
                    if (wsel == 0) { v0 *= QSCALE; v1 *= QSCALE; }
                    else { v0 += g_pe[t * DK + d]; v1 += g_pe[t * DK + d + 1]; }
                    float2 o;
                    o.x = f2tff(v0); o.y = f2tff(v1);
                    *(float2*)(dstbase + (((size_t)(b * N_HEADS + h) * SEQ + t) * DK + d)) = o;
                }
            }
        }
    }
}

// ---------------- output projection ------------------------------------------
__global__ __launch_bounds__(256) void out_tc(const float* __restrict__ bo,
                                              float* __restrict__ out)
{
    extern __shared__ char smem[];
    int tid = threadIdx.x, wid = tid >> 5, lane = tid & 31;
    int m0 = blockIdx.x * 128;
    int n0 = blockIdx.y * 128;

    float acc[4][4][4];
    #pragma unroll
    for (int a = 0; a < 4; a++)
        #pragma unroll
        for (int b = 0; b < 4; b++)
            #pragma unroll
            for (int c = 0; c < 4; c++) acc[a][b][c] = 0.f;

    gemm_mainloop(g_ctx, g_wr + 3 * 262144, m0, n0, smem, acc);

    int wm = (wid >> 2) * 64, wn = (wid & 3) * 32;
    #pragma unroll
    for (int mi = 0; mi < 4; mi++) {
        #pragma unroll
        for (int rr = 0; rr < 2; rr++) {
            int m = m0 + wm + mi * 16 + (lane >> 2) + rr * 8;
            #pragma unroll
            for (int nj = 0; nj < 4; nj++) {
                int n = n0 + wn + nj * 8 + (lane & 3) * 2;
                float2 v;
                v.x = acc[mi][nj][rr * 2]     + bo[n];
                v.y = acc[mi][nj][rr * 2 + 1] + bo[n + 1];
                *(float2*)(out + (size_t)m * 512 + n) = v;
            }
        }
    }
}

// ---------------- flash attention (tf32 mma.sync) ----------------------------
// CTA: 64 q-rows, 128 threads (4 warps each owning m16). K/V tile = 64.
// Q staging buffer reused for P after the one-time ldmatrix (warp-private rows).
// V double-buffered, K single-buffered with covered prefetch.
// smem: QP@0 16KB, K@16384 16KB, V0@32768 16KB, V1@49152 16KB = 64KB
//       -> 3 CTAs/SM, regs unconstrained.
#define ATTN_SMEM 65536

__global__ __launch_bounds__(128) void attn_tc() {
    extern __shared__ char smem[];
    uint32_t sQP = smem_u32(smem);
    uint32_t sK  = sQP + 16384;
    uint32_t sV0 = sQP + 32768;
    int tid = threadIdx.x, wid = tid >> 5, lane = tid & 31;
    int bh = blockIdx.z * N_HEADS + blockIdx.y;
    int q0 = blockIdx.x * 64;
    const float* Qb  = g_q  + (size_t)bh * SEQ * DK;
    const float* Kb  = g_k  + (size_t)bh * SEQ * DK;
    const float* Vtb = g_vt + (size_t)bh * DK * SEQ;

    // stage Q + K tile 0 + V tile 0
    #pragma unroll
    for (int i = 0; i < 8; i++) {
        int id = tid + i * 128, r = id >> 4, c = id & 15;
        uint32_t off = (r * 16 + (c ^ (r & 7))) * 16;
        CP16(sQP + off, Qb + (size_t)(q0 + r) * DK + c * 4);
        CP16(sK  + off, Kb + (size_t)r * DK + c * 4);
        CP16(sV0 + off, Vtb + (size_t)r * SEQ + c * 4);
    }
    CP_COMMIT();
    CP_WAIT0();
    __syncthreads();

    // Q fragments resident in registers: one-time ldmatrix (warp-private rows).
    uint32_t qf[8][4];
    #pragma unroll
    for (int ks = 0; ks < 8; ks++) {
        int r = wid * 16 + (lane & 15);
        int c = 2 * ks + (lane >> 4);
        LDSM4(qf[ks][0], qf[ks][1], qf[ks][2], qf[ks][3],
              sQP + (r * 16 + (c ^ (r & 7))) * 16);
    }

    float accO[8][4];
    #pragma unroll
    for (int nj = 0; nj < 8; nj++)
        #pragma unroll
        for (int k = 0; k < 4; k++) accO[nj][k] = 0.f;
    float mrun0 = -1e30f, mrun1 = -1e30f, l0 = 0.f, l1 = 0.f;

    for (int it = 0; it < 32; it++) {
        uint32_t vb    = sV0 + (uint32_t)(it & 1) * 16384;
        uint32_t vbalt = sV0 + (uint32_t)(1 - (it & 1)) * 16384;
        int s0n = (it + 1) * 64;

        // ---- prefetch V(it+1) into the alternate buffer (covered by full iter)
        if (it < 31) {
            #pragma unroll
            for (int i = 0; i < 8; i++) {
                int id = tid + i * 128, r = id >> 4, c = id & 15;
                uint32_t off = (r * 16 + (c ^ (r & 7))) * 16;
                CP16(vbalt + off, Vtb + (size_t)r * SEQ + s0n + c * 4);
            }
            CP_COMMIT();
        }

        // ---- S' = (QSCALE*Q) @ K^T : per-warp m16 x n64, k=64 (8 ksteps) ----
        float s[8][4];
        #pragma unroll
        for (int nj = 0; nj < 8; nj++)
            #pragma unroll
            for (int k = 0; k < 4; k++) s[nj][k] = 0.f;
        #pragma unroll
        for (int ks = 0; ks < 8; ks++) {
            #pragma unroll
            for (int nj2 = 0; nj2 < 4; nj2++) {
                int r = nj2 * 16 + (lane & 7) + ((lane >> 4) << 3);
                int c = 2 * ks + ((lane >> 3) & 1);
                uint32_t t0, t1, t2, t3;
                LDSM4(t0, t1, t2, t3, sK + (r * 16 + (c ^ (r & 7))) * 16);
                uint32_t b0[2] = {t0, t1}, b1[2] = {t2, t3};
                MMA_TF32(s[nj2 * 2], qf[ks], b0);
                MMA_TF32(s[nj2 * 2 + 1], qf[ks], b1);
            }
        }
        __syncthreads();               // all warps done reading sK

        // ---- prefetch K(it+1) into sK (covered by softmax + P + PV) ----
        if (it < 31) {
            #pragma unroll
            for (int i = 0; i < 8; i++) {
                int id = tid + i * 128, r = id >> 4, c = id & 15;
                uint32_t off = (r * 16 + (c ^ (r & 7))) * 16;
                CP16(sK + off, Kb + (size_t)(s0n + r) * DK + c * 4);
            }
            CP_COMMIT();
        }

        // ---- online softmax in base-2 domain (rows g and g+8 per lane) ----
        float ml0 = -1e30f, ml1 = -1e30f;
        #pragma unroll
        for (int nj = 0; nj < 8; nj++) {
            ml0 = fmaxf(ml0, fmaxf(s[nj][0], s[nj][1]));
            ml1 = fmaxf(ml1, fmaxf(s[nj][2], s[nj][3]));
        }
        ml0 = fmaxf(ml0, __shfl_xor_sync(0xffffffffu, ml0, 1));
        ml0 = fmaxf(ml0, __shfl_xor_sync(0xffffffffu, ml0, 2));
        ml1 = fmaxf(ml1, __shfl_xor_sync(0xffffffffu, ml1, 1));
        ml1 = fmaxf(ml1, __shfl_xor_sync(0xffffffffu, ml1, 2));
        float mn0 = fmaxf(mrun0, ml0), mn1 = fmaxf(mrun1, ml1);
        float al0 = ex2(mrun0 - mn0), al1 = ex2(mrun1 - mn1);
        float rs0 = 0.f, rs1 = 0.f;
        #pragma unroll
        for (int nj = 0; nj < 8; nj++) {
            s[nj][0] = ex2(s[nj][0] - mn0);
            s[nj][1] = ex2(s[nj][1] - mn0);
            s[nj][2] = ex2(s[nj][2] - mn1);
            s[nj][3] = ex2(s[nj][3] - mn1);
            rs0 += s[nj][0] + s[nj][1];
            rs1 += s[nj][2] + s[nj][3];
        }
        rs0 += __shfl_xor_sync(0xffffffffu, rs0, 1);
        rs0 += __shfl_xor_sync(0xffffffffu, rs0, 2);
        rs1 += __shfl_xor_sync(0xffffffffu, rs1, 1);
        rs1 += __shfl_xor_sync(0xffffffffu, rs1, 2);
        l0 = l0 * al0 + rs0;  l1 = l1 * al1 + rs1;
        mrun0 = mn0;          mrun1 = mn1;
        #pragma unroll
        for (int nj = 0; nj < 8; nj++) {
            accO[nj][0] *= al0; accO[nj][1] *= al0;
            accO[nj][2] *= al1; accO[nj][3] *= al1;
        }

        // ---- store P (tf32-rounded) into QP buffer, A-operand layout ----
        {
            int r0 = wid * 16 + (lane >> 2), r1 = r0 + 8;
            int off8 = (lane & 1) * 8;
            #pragma unroll
            for (int nj = 0; nj < 8; nj++) {
                int col = nj * 8 + (lane & 3) * 2;
                int ch = col >> 2;
                STS64(sQP + (r0 * 16 + (ch ^ (r0 & 7))) * 16 + off8,
                      f2tf(s[nj][0]), f2tf(s[nj][1]));
                STS64(sQP + (r1 * 16 + (ch ^ (r1 & 7))) * 16 + off8,
                      f2tf(s[nj][2]), f2tf(s[nj][3]));
            }
        }
        __syncwarp();

        // ---- O += P @ V : per-warp m16 x n64(d), k=64(s) ----
        #pragma unroll
        for (int ks = 0; ks < 8; ks++) {
            uint32_t af[4];
            {
                int r = wid * 16 + (lane & 15);
                int c = 2 * ks + (lane >> 4);
                LDSM4(af[0], af[1], af[2], af[3], sQP + (r * 16 + (c ^ (r & 7))) * 16);
            }
            #pragma unroll
            for (int nj2 = 0; nj2 < 4; nj2++) {
                int r = nj2 * 16 + (lane & 7) + ((lane >> 4) << 3);
                int c = 2 * ks + ((lane >> 3) & 1);
                uint32_t t0, t1, t2, t3;
                LDSM4(t0, t1, t2, t3, vb + (r * 16 + (c ^ (r & 7))) * 16);
                uint32_t b0[2] = {t0, t1}, b1[2] = {t2, t3};
                MMA_TF32(accO[nj2 * 2], af, b0);
                MMA_TF32(accO[nj2 * 2 + 1], af, b1);
            }
        }

        // ---- wait for K(it+1)/V(it+1) and make them visible ----
        if (it < 31) {
            CP_WAIT0();
        }
        __syncthreads();
    }

    // ---- epilogue: normalize, round, write to g_ctx ----
    float inv0 = 1.0f / l0, inv1 = 1.0f / l1;
    int t0 = q0 + wid * 16 + (lane >> 2), t1 = t0 + 8;
    float* dst = g_ctx + (size_t)blockIdx.z * SEQ * D_MODEL + (size_t)blockIdx.y * DK;
    #pragma unroll
    for (int nj = 0; nj < 8; nj++) {
        int col = nj * 8 + (lane & 3) * 2;
        float2 v0, v1;
        v0.x = f2tff(accO[nj][0] * inv0); v0.y = f2tff(accO[nj][1] * inv0);
        v1.x = f2tff(accO[nj][2] * inv1); v1.y = f2tff(accO[nj][3] * inv1);
        *(float2*)(dst + (size_t)t0 * D_MODEL + col) = v0;
        *(float2*)(dst + (size_t)t1 * D_MODEL + col) = v1;
    }
}

// ---------------- launch -----------------------------------------------------
extern "C" void kernel_launch(void* const* d_in, const int* in_sizes, int n_in,
                              void* d_out, int out_size) {
    const float* x    = (const float*)d_in[0];
    const float* ln_g = (const float*)d_in[1];
    const float* ln_b = (const float*)d_in[2];
    const float* wq   = (const float*)d_in[3];
    const float* bq   = (const float*)d_in[4];
    const float* wk   = (const float*)d_in[5];
    const float* bk   = (const float*)d_in[6];
    const float* wv   = (const float*)d_in[7];
    const float* bv   = (const float*)d_in[8];
    const float* wo   = (const float*)d_in[9];
    const float* bo   = (const float*)d_in[10];

    cudaFuncSetAttribute(qkv_tc,  cudaFuncAttributeMaxDynamicSharedMemorySize, GEMM_SMEM);
    cudaFuncSetAttribute(out_tc,  cudaFuncAttributeMaxDynamicSharedMemorySize, GEMM_SMEM);
    cudaFuncSetAttribute(attn_tc, cudaFuncAttributeMaxDynamicSharedMemorySize, ATTN_SMEM);

    prep_kernel<<<1024, 256>>>(wq, wk, wv, wo);
    ln_kernel<<<BT, 128>>>(x, ln_g, ln_b);
    qkv_tc<<<dim3(64, 12), 256, GEMM_SMEM>>>(bq, bk, bv);
    attn_tc<<<dim3(32, 8, 4), 128, ATTN_SMEM>>>();
    out_tc<<<dim3(64, 4), 256, GEMM_SMEM>>>(bo, (float*)d_out);
}